// round 1
// baseline (speedup 1.0000x reference)
#include <cuda_runtime.h>
#include <math.h>

#define BB 2048
#define DD 1024
#define UU 1024
#define HHU 256
#define FOURU (4*UU)    // 4096
#define FOURHU (4*HHU)  // 1024

// ---- scratch (static device arrays; no allocation allowed) ----
__device__ float g_z [BB * FOURHU];   // [2048,1024]
__device__ float g_dx[BB * FOURU];    // [2048,4096]
__device__ float g_dh[BB * FOURU];
__device__ float g_db[BB * FOURU];
__device__ float g_px[BB * FOURU];
__device__ float g_ph[BB * FOURU];

__device__ __forceinline__ float sigf(float x) { return 1.0f / (1.0f + expf(-x)); }

// ============================================================================
// SGEMM: C[M,N] = A[M,K] @ W[K,N] (+ bias[N]) (+ beta*Cold)
// Row-major everywhere. BM=BN=128, BK=8, TM=TN=8, 256 threads.
// All problem dims here are multiples of the tiles -> no bounds checks.
// ============================================================================
__global__ __launch_bounds__(256, 2)
void sgemm128(const float* __restrict__ A, const float* __restrict__ Wt,
              const float* __restrict__ bias, float* __restrict__ C,
              int M, int N, int K, int beta)
{
    constexpr int BM = 128, BN = 128, BK = 8, TM = 8, TN = 8;
    __shared__ float As[BK][BM];
    __shared__ float Ws[BK][BN];

    const int tid = threadIdx.x;
    const int bx = blockIdx.x;   // N tile
    const int by = blockIdx.y;   // M tile

    const float* Ab = A + (size_t)by * BM * K;
    const float* Wb = Wt + (size_t)bx * BN;

    const int aRow = tid >> 1;          // 0..127
    const int aCol = (tid & 1) * 4;     // 0 or 4
    const int wRow = tid >> 5;          // 0..7
    const int wCol = (tid & 31) * 4;    // 0..124
    const int ty = tid >> 4;            // 0..15
    const int tx = tid & 15;            // 0..15

    float acc[TM][TN];
    #pragma unroll
    for (int m = 0; m < TM; m++)
        #pragma unroll
        for (int n = 0; n < TN; n++) acc[m][n] = 0.0f;

    for (int k0 = 0; k0 < K; k0 += BK) {
        float4 av = *(const float4*)(Ab + (size_t)aRow * K + k0 + aCol);
        As[aCol + 0][aRow] = av.x;
        As[aCol + 1][aRow] = av.y;
        As[aCol + 2][aRow] = av.z;
        As[aCol + 3][aRow] = av.w;
        float4 wv = *(const float4*)(Wb + (size_t)(k0 + wRow) * N + wCol);
        *(float4*)&Ws[wRow][wCol] = wv;
        __syncthreads();

        #pragma unroll
        for (int kk = 0; kk < BK; kk++) {
            float ra[TM], rw[TN];
            float4 a0 = *(const float4*)&As[kk][ty * TM];
            float4 a1 = *(const float4*)&As[kk][ty * TM + 4];
            ra[0]=a0.x; ra[1]=a0.y; ra[2]=a0.z; ra[3]=a0.w;
            ra[4]=a1.x; ra[5]=a1.y; ra[6]=a1.z; ra[7]=a1.w;
            float4 w0 = *(const float4*)&Ws[kk][tx * TN];
            float4 w1 = *(const float4*)&Ws[kk][tx * TN + 4];
            rw[0]=w0.x; rw[1]=w0.y; rw[2]=w0.z; rw[3]=w0.w;
            rw[4]=w1.x; rw[5]=w1.y; rw[6]=w1.z; rw[7]=w1.w;
            #pragma unroll
            for (int m = 0; m < TM; m++)
                #pragma unroll
                for (int n = 0; n < TN; n++)
                    acc[m][n] = fmaf(ra[m], rw[n], acc[m][n]);
        }
        __syncthreads();
    }

    #pragma unroll
    for (int m = 0; m < TM; m++) {
        int row = by * BM + ty * TM + m;
        float* Crow = C + (size_t)row * N + bx * BN + tx * TN;
        #pragma unroll
        for (int n = 0; n < TN; n++) {
            float v = acc[m][n];
            if (bias) v += bias[bx * BN + tx * TN + n];
            if (beta) v += Crow[n];
            Crow[n] = v;
        }
    }
}

// ============================================================================
// Hyper LSTM pointwise: from z[B,4*HU] and hyper_c[B,HU]
// -> hyper_out[B,HU] (into d_out), hyper_c_new[B,HU] (into d_out)
// ============================================================================
__global__ void hyper_pointwise(const float* __restrict__ z,
                                const float* __restrict__ hyper_c,
                                float* __restrict__ hyper_out,
                                float* __restrict__ hyper_c_new)
{
    int idx = blockIdx.x * blockDim.x + threadIdx.x;
    if (idx >= BB * HHU) return;
    int b = idx / HHU;
    int u = idx - b * HHU;
    const float* zr = z + (size_t)b * FOURHU;
    float hi = zr[u];
    float hf = zr[HHU + u];
    float hg = zr[2 * HHU + u];
    float ho = zr[3 * HHU + u];
    float c = sigf(hf) * hyper_c[idx] + sigf(hi) * tanhf(hg);
    hyper_c_new[idx] = c;
    hyper_out[idx] = sigf(ho) * tanhf(c);
}

// ============================================================================
// Main epilogue: per batch row b (grid=2048, 512 threads)
//   s = d_x*proj_x + d_h*proj_h + d_b           (4096 elems)
//   gates = LN(s) ; i,f,g,o = split(gates)
//   c_new = sig(f)*main_c + sig(i)*tanh(g)      (1024 elems)
//   h_new = sig(o)*tanh(LN(c_new))
// Thread t holds s at j = t + 512*r, r=0..7 -> (i,i,f,f,g,g,o,o) for
// c-indices u0=t, u1=t+512.
// ============================================================================
__device__ __forceinline__ void block_reduce2(float& a, float& b, float* sm)
{
    __syncthreads();  // protect smem reuse across calls
    #pragma unroll
    for (int o = 16; o > 0; o >>= 1) {
        a += __shfl_down_sync(0xffffffffu, a, o);
        b += __shfl_down_sync(0xffffffffu, b, o);
    }
    int w = threadIdx.x >> 5, l = threadIdx.x & 31;
    if (l == 0) { sm[w] = a; sm[32 + w] = b; }
    __syncthreads();
    if (w == 0) {
        int nw = blockDim.x >> 5;
        a = (l < nw) ? sm[l] : 0.0f;
        b = (l < nw) ? sm[32 + l] : 0.0f;
        #pragma unroll
        for (int o = 16; o > 0; o >>= 1) {
            a += __shfl_down_sync(0xffffffffu, a, o);
            b += __shfl_down_sync(0xffffffffu, b, o);
        }
        if (l == 0) { sm[0] = a; sm[32] = b; }
    }
    __syncthreads();
    a = sm[0];
    b = sm[32];
}

__global__ __launch_bounds__(512)
void main_epilogue(const float* __restrict__ dx, const float* __restrict__ dh,
                   const float* __restrict__ dbv, const float* __restrict__ px,
                   const float* __restrict__ ph, const float* __restrict__ main_c,
                   float* __restrict__ out_h, float* __restrict__ out_c)
{
    __shared__ float sm[64];
    const int b = blockIdx.x;
    const int t = threadIdx.x;
    const size_t base = (size_t)b * FOURU;

    float s[8];
    float sum = 0.0f, sq = 0.0f;
    #pragma unroll
    for (int r = 0; r < 8; r++) {
        int j = t + r * 512;
        float v = fmaf(dx[base + j], px[base + j],
                  fmaf(dh[base + j], ph[base + j], dbv[base + j]));
        s[r] = v;
        sum += v;
        sq = fmaf(v, v, sq);
    }
    block_reduce2(sum, sq, sm);
    float mean = sum * (1.0f / 4096.0f);
    float var = sq * (1.0f / 4096.0f) - mean * mean;
    float inv = rsqrtf(var + 1e-3f);

    float i0 = (s[0] - mean) * inv, i1 = (s[1] - mean) * inv;
    float f0 = (s[2] - mean) * inv, f1 = (s[3] - mean) * inv;
    float g0 = (s[4] - mean) * inv, g1 = (s[5] - mean) * inv;
    float o0 = (s[6] - mean) * inv, o1 = (s[7] - mean) * inv;

    const size_t cb = (size_t)b * UU;
    float c0 = sigf(f0) * main_c[cb + t]       + sigf(i0) * tanhf(g0);
    float c1 = sigf(f1) * main_c[cb + t + 512] + sigf(i1) * tanhf(g1);

    float sum2 = c0 + c1;
    float sq2 = fmaf(c0, c0, c1 * c1);
    block_reduce2(sum2, sq2, sm);
    float mean2 = sum2 * (1.0f / 1024.0f);
    float var2 = sq2 * (1.0f / 1024.0f) - mean2 * mean2;
    float inv2 = rsqrtf(var2 + 1e-3f);

    float h0 = sigf(o0) * tanhf((c0 - mean2) * inv2);
    float h1 = sigf(o1) * tanhf((c1 - mean2) * inv2);

    out_c[cb + t] = c0;
    out_c[cb + t + 512] = c1;
    out_h[cb + t] = h0;
    out_h[cb + t + 512] = h1;
}

// ============================================================================
// Launch
// ============================================================================
extern "C" void kernel_launch(void* const* d_in, const int* in_sizes, int n_in,
                              void* d_out, int out_size)
{
    const float* inputs       = (const float*)d_in[0];   // [2048,1024]
    const float* main_h       = (const float*)d_in[1];   // [2048,1024]
    const float* main_c       = (const float*)d_in[2];   // [2048,1024]
    const float* hyper_h      = (const float*)d_in[3];   // [2048,256]
    const float* hyper_c      = (const float*)d_in[4];   // [2048,256]
    const float* kernel_w     = (const float*)d_in[5];   // [1024,4096]
    const float* rec_w        = (const float*)d_in[6];   // [1024,4096]
    const float* bias         = (const float*)d_in[7];   // [4096]
    const float* hyper_kernel = (const float*)d_in[8];   // [2048,1024]
    const float* hyper_rec    = (const float*)d_in[9];   // [256,1024]
    const float* hyper_bias   = (const float*)d_in[10];  // [1024]
    const float* dx_w         = (const float*)d_in[11];  // [256,4096]
    const float* dx_b         = (const float*)d_in[12];
    const float* dh_w         = (const float*)d_in[13];
    const float* dh_b         = (const float*)d_in[14];
    const float* db_w         = (const float*)d_in[15];
    const float* db_b         = (const float*)d_in[16];

    float* out = (float*)d_out;
    // output layout: main_h_new | main_c_new | hyper_out | hyper_c_new
    float* out_h  = out;
    float* out_c  = out + (size_t)BB * UU;
    float* out_ho = out + (size_t)2 * BB * UU;
    float* out_hc = out_ho + (size_t)BB * HHU;

    float *z, *dx, *dh, *db_, *px, *ph;
    cudaGetSymbolAddress((void**)&z,   g_z);
    cudaGetSymbolAddress((void**)&dx,  g_dx);
    cudaGetSymbolAddress((void**)&dh,  g_dh);
    cudaGetSymbolAddress((void**)&db_, g_db);
    cudaGetSymbolAddress((void**)&px,  g_px);
    cudaGetSymbolAddress((void**)&ph,  g_ph);

    // ---- hyper cell GEMMs: z = inputs@hk[0:1024] + main_h@hk[1024:2048]
    //                            + hyper_h@hrk + hyper_bias ----
    {
        dim3 grid(FOURHU / 128, BB / 128);   // (8,16)
        sgemm128<<<grid, 256>>>(inputs, hyper_kernel, hyper_bias, z,
                                BB, FOURHU, DD, 0);
        sgemm128<<<grid, 256>>>(main_h, hyper_kernel + (size_t)DD * FOURHU,
                                nullptr, z, BB, FOURHU, UU, 1);
        sgemm128<<<grid, 256>>>(hyper_h, hyper_rec, nullptr, z,
                                BB, FOURHU, HHU, 1);
    }

    // ---- hyper pointwise -> hyper_out / hyper_c_new (into d_out) ----
    hyper_pointwise<<<(BB * HHU + 255) / 256, 256>>>(z, hyper_c, out_ho, out_hc);

    // ---- hypernet scaling GEMMs (K=256) ----
    {
        dim3 grid(FOURU / 128, BB / 128);    // (32,16)
        sgemm128<<<grid, 256>>>(out_ho, dx_w, dx_b, dx, BB, FOURU, HHU, 0);
        sgemm128<<<grid, 256>>>(out_ho, dh_w, dh_b, dh, BB, FOURU, HHU, 0);
        sgemm128<<<grid, 256>>>(out_ho, db_w, db_b, db_, BB, FOURU, HHU, 0);
        // ---- main projections (K=1024) ----
        sgemm128<<<grid, 256>>>(inputs, kernel_w, bias, px, BB, FOURU, DD, 0);
        sgemm128<<<grid, 256>>>(main_h, rec_w, nullptr, ph, BB, FOURU, UU, 0);
    }

    // ---- fused LN + LSTM epilogue ----
    main_epilogue<<<BB, 512>>>(dx, dh, db_, px, ph, main_c, out_h, out_c);
}

// round 3
// speedup vs baseline: 2.2831x; 2.2831x over previous
#include <cuda_runtime.h>
#include <cuda_bf16.h>
#include <math.h>
#include <cstdint>

#define BB 2048
#define DD 1024
#define UU 1024
#define HHU 256
#define FOURU (4*UU)     // 4096
#define FOURHU (4*HHU)   // 1024
#define KHYP (DD+UU+HHU) // 2304

typedef __nv_bfloat16 bf16;

// ---------------------------------------------------------------------------
// scratch (static device arrays; no allocation allowed)
// ---------------------------------------------------------------------------
__device__ float g_z [BB * FOURHU];
__device__ float g_dx[BB * FOURU];
__device__ float g_dh[BB * FOURU];
__device__ float g_db[BB * FOURU];
__device__ float g_px[BB * FOURU];
__device__ float g_ph[BB * FOURU];

// split activations: [inputs | main_h | hyper_h] concat along K -> [2048, 2304]
__device__ bf16 g_ahyp_h[BB * KHYP];
__device__ bf16 g_ahyp_l[BB * KHYP];
// split hyper_out [2048, 256]
__device__ bf16 g_aho_h[BB * HHU];
__device__ bf16 g_aho_l[BB * HHU];
// transposed + split weights ([N, K] row-major)
__device__ bf16 g_wthyp_h[FOURHU * KHYP];
__device__ bf16 g_wthyp_l[FOURHU * KHYP];
__device__ bf16 g_wtdx_h[FOURU * HHU];
__device__ bf16 g_wtdx_l[FOURU * HHU];
__device__ bf16 g_wtdh_h[FOURU * HHU];
__device__ bf16 g_wtdh_l[FOURU * HHU];
__device__ bf16 g_wtdb_h[FOURU * HHU];
__device__ bf16 g_wtdb_l[FOURU * HHU];
__device__ bf16 g_wtk_h[FOURU * UU];
__device__ bf16 g_wtk_l[FOURU * UU];
__device__ bf16 g_wtr_h[FOURU * UU];
__device__ bf16 g_wtr_l[FOURU * UU];

__device__ __forceinline__ float sigf(float x) { return 1.0f / (1.0f + expf(-x)); }

__device__ __forceinline__ uint32_t smem_u32(const void* p) {
    uint32_t a;
    asm("{ .reg .u64 t; cvta.to.shared.u64 t, %1; cvt.u32.u64 %0, t; }" : "=r"(a) : "l"(p));
    return a;
}
__device__ __forceinline__ void cpa16(uint32_t dst, const void* src) {
    asm volatile("cp.async.cg.shared.global [%0], [%1], 16;" :: "r"(dst), "l"(src));
}
#define CP_COMMIT() asm volatile("cp.async.commit_group;" ::: "memory")
#define CP_WAIT(n)  asm volatile("cp.async.wait_group %0;" :: "n"(n) : "memory")

__device__ __forceinline__ void ldsm4(uint32_t& r0, uint32_t& r1, uint32_t& r2, uint32_t& r3,
                                      uint32_t addr) {
    asm volatile("ldmatrix.sync.aligned.m8n8.x4.shared.b16 {%0,%1,%2,%3}, [%4];"
                 : "=r"(r0), "=r"(r1), "=r"(r2), "=r"(r3) : "r"(addr));
}
__device__ __forceinline__ void mma_bf16(float* c, const uint32_t* a, uint32_t b0, uint32_t b1) {
    asm volatile("mma.sync.aligned.m16n8k16.row.col.f32.bf16.bf16.f32 "
                 "{%0,%1,%2,%3}, {%4,%5,%6,%7}, {%8,%9}, {%0,%1,%2,%3};"
                 : "+f"(c[0]), "+f"(c[1]), "+f"(c[2]), "+f"(c[3])
                 : "r"(a[0]), "r"(a[1]), "r"(a[2]), "r"(a[3]), "r"(b0), "r"(b1));
}

// ---------------------------------------------------------------------------
// split-bf16 HMMA GEMM: C[M,N] = (Ah+Al)[M,K] @ (Wh+Wl)[N,K]^T (+bias)
// CTA tile 128x128, BK=32, double-buffered cp.async, 256 threads (8 warps 4x2)
// smem rows padded to 80 bytes (40 bf16) -> conflict-free ldmatrix.
// ---------------------------------------------------------------------------
#define SROW_B   80
#define TILE_B   (128 * SROW_B)   // 10240 B per matrix
#define STAGE_B  (4 * TILE_B)     // Ah, Al, Wh, Wl
#define GEMM_SMEM (2 * STAGE_B)   // 81920 B

__global__ __launch_bounds__(256, 1)
void gemm_mma(const bf16* __restrict__ Ah, const bf16* __restrict__ Al, int lda,
              const bf16* __restrict__ Wh, const bf16* __restrict__ Wl, int ldw,
              const float* __restrict__ bias, float* __restrict__ C,
              int N, int K)
{
    extern __shared__ char smem[];
    const uint32_t sb = smem_u32(smem);
    const int tid  = threadIdx.x;
    const int lane = tid & 31;
    const int wid  = tid >> 5;
    const int warp_m = wid & 3;   // 0..3 -> 32-row slice
    const int warp_n = wid >> 2;  // 0..1 -> 64-col slice
    const int m0 = blockIdx.y * 128;
    const int n0 = blockIdx.x * 128;

    const bf16* pAh = Ah + (size_t)m0 * lda;
    const bf16* pAl = Al + (size_t)m0 * lda;
    const bf16* pWh = Wh + (size_t)n0 * ldw;
    const bf16* pWl = Wl + (size_t)n0 * ldw;

    float acc[2][8][4];
    #pragma unroll
    for (int a = 0; a < 2; a++)
        #pragma unroll
        for (int b = 0; b < 8; b++)
            #pragma unroll
            for (int c = 0; c < 4; c++) acc[a][b][c] = 0.0f;

    // ldmatrix fragment address components (same pattern for A and W)
    const uint32_t fr = (lane & 7) + ((lane >> 3) & 1) * 8;  // row within 16
    const uint32_t fcb = ((lane >> 4) * 8) * 2;              // byte col offset

    const int ldr = tid >> 2;       // load row 0..63 (x2 iters -> 128)
    const int ldc = (tid & 3) * 8;  // load col in elems (x16B chunks)

    const int nch = K / 32;

    // ---- preload stage 0 ----
    {
        const bf16* ps[4] = {pAh, pAl, pWh, pWl};
        const int lds[4] = {lda, lda, ldw, ldw};
        #pragma unroll
        for (int m = 0; m < 4; m++)
            #pragma unroll
            for (int i = 0; i < 2; i++) {
                int row = ldr + i * 64;
                cpa16(sb + m * TILE_B + row * SROW_B + (ldc >> 3) * 16,
                      ps[m] + (size_t)row * lds[m] + ldc);
            }
        CP_COMMIT();
    }

    for (int kc = 0; kc < nch; kc++) {
        if (kc + 1 < nch) {
            const uint32_t base = sb + ((kc + 1) & 1) * STAGE_B;
            const int k0 = (kc + 1) * 32;
            const bf16* ps[4] = {pAh, pAl, pWh, pWl};
            const int lds[4] = {lda, lda, ldw, ldw};
            #pragma unroll
            for (int m = 0; m < 4; m++)
                #pragma unroll
                for (int i = 0; i < 2; i++) {
                    int row = ldr + i * 64;
                    cpa16(base + m * TILE_B + row * SROW_B + (ldc >> 3) * 16,
                          ps[m] + (size_t)row * lds[m] + k0 + ldc);
                }
            CP_COMMIT();
            CP_WAIT(1);
        } else {
            CP_WAIT(0);
        }
        __syncthreads();

        const uint32_t stg = sb + (kc & 1) * STAGE_B;
        #pragma unroll
        for (int s = 0; s < 2; s++) {
            const uint32_t kb = s * 32 + fcb;   // byte offset in row for this kstep
            uint32_t ah[2][4], al[2][4];
            #pragma unroll
            for (int mt = 0; mt < 2; mt++) {
                uint32_t ra = stg + (warp_m * 32 + mt * 16 + fr) * SROW_B + kb;
                ldsm4(ah[mt][0], ah[mt][1], ah[mt][2], ah[mt][3], ra);
                ldsm4(al[mt][0], al[mt][1], al[mt][2], al[mt][3], ra + TILE_B);
            }
            #pragma unroll
            for (int np = 0; np < 4; np++) {
                uint32_t wh[4], wl[4];
                uint32_t rw = stg + 2 * TILE_B + (warp_n * 64 + np * 16 + fr) * SROW_B + kb;
                ldsm4(wh[0], wh[1], wh[2], wh[3], rw);
                ldsm4(wl[0], wl[1], wl[2], wl[3], rw + TILE_B);
                #pragma unroll
                for (int mt = 0; mt < 2; mt++) {
                    mma_bf16(acc[mt][2*np],   ah[mt], wh[0], wh[2]);
                    mma_bf16(acc[mt][2*np],   ah[mt], wl[0], wl[2]);
                    mma_bf16(acc[mt][2*np],   al[mt], wh[0], wh[2]);
                    mma_bf16(acc[mt][2*np+1], ah[mt], wh[1], wh[3]);
                    mma_bf16(acc[mt][2*np+1], ah[mt], wl[1], wl[3]);
                    mma_bf16(acc[mt][2*np+1], al[mt], wh[1], wh[3]);
                }
            }
        }
        __syncthreads();
    }

    // ---- epilogue ----
    const int er = lane >> 2;
    const int ec = (lane & 3) * 2;
    #pragma unroll
    for (int mt = 0; mt < 2; mt++) {
        const int row = m0 + warp_m * 32 + mt * 16 + er;
        #pragma unroll
        for (int nt = 0; nt < 8; nt++) {
            const int col = n0 + warp_n * 64 + nt * 8 + ec;
            float b0 = 0.f, b1 = 0.f;
            if (bias) { b0 = bias[col]; b1 = bias[col + 1]; }
            float2 v0 = make_float2(acc[mt][nt][0] + b0, acc[mt][nt][1] + b1);
            float2 v1 = make_float2(acc[mt][nt][2] + b0, acc[mt][nt][3] + b1);
            *(float2*)(C + (size_t)row * N + col) = v0;
            *(float2*)(C + (size_t)(row + 8) * N + col) = v1;
        }
    }
}

// ---------------------------------------------------------------------------
// prep: concat + split activations -> [2048, 2304] hi/lo
// ---------------------------------------------------------------------------
__global__ void concat_split(const float* __restrict__ inputs,
                             const float* __restrict__ main_h,
                             const float* __restrict__ hyper_h,
                             bf16* __restrict__ Dh, bf16* __restrict__ Dl)
{
    int i4 = blockIdx.x * blockDim.x + threadIdx.x;
    if (i4 >= BB * KHYP / 4) return;
    int row = i4 / (KHYP / 4);
    int c4  = (i4 - row * (KHYP / 4)) * 4;
    const float* src;
    if (c4 < DD)            src = inputs  + (size_t)row * DD  + c4;
    else if (c4 < DD + UU)  src = main_h  + (size_t)row * UU  + (c4 - DD);
    else                    src = hyper_h + (size_t)row * HHU + (c4 - DD - UU);
    float4 v = *(const float4*)src;
    size_t o = (size_t)row * KHYP + c4;
    float a[4] = {v.x, v.y, v.z, v.w};
    #pragma unroll
    for (int j = 0; j < 4; j++) {
        bf16 h = __float2bfloat16(a[j]);
        Dh[o + j] = h;
        Dl[o + j] = __float2bfloat16(a[j] - __bfloat162float(h));
    }
}

// ---------------------------------------------------------------------------
// prep: transpose + split weight W[K,N] -> Th,Tl [N, dstLd] at column kOff
// ---------------------------------------------------------------------------
__global__ void trans_split(const float* __restrict__ W,
                            bf16* __restrict__ Th, bf16* __restrict__ Tl,
                            int K, int N, int dstLd, int kOff)
{
    __shared__ float t[32][33];
    const int n0 = blockIdx.x * 32, k0 = blockIdx.y * 32;
    const int tx = threadIdx.x, ty = threadIdx.y;   // 32 x 8
    #pragma unroll
    for (int i = 0; i < 4; i++)
        t[ty + i * 8][tx] = W[(size_t)(k0 + ty + i * 8) * N + n0 + tx];
    __syncthreads();
    #pragma unroll
    for (int i = 0; i < 4; i++) {
        int n = ty + i * 8;
        float v = t[tx][n];
        bf16 h = __float2bfloat16(v);
        size_t o = (size_t)(n0 + n) * dstLd + kOff + k0 + tx;
        Th[o] = h;
        Tl[o] = __float2bfloat16(v - __bfloat162float(h));
    }
}

// ---------------------------------------------------------------------------
// hyper LSTM pointwise (+ bf16 split of hyper_out)
// ---------------------------------------------------------------------------
__global__ void hyper_pointwise(const float* __restrict__ z,
                                const float* __restrict__ hyper_c,
                                float* __restrict__ hyper_out,
                                float* __restrict__ hyper_c_new,
                                bf16* __restrict__ hoh, bf16* __restrict__ hol)
{
    int idx = blockIdx.x * blockDim.x + threadIdx.x;
    if (idx >= BB * HHU) return;
    int b = idx / HHU;
    int u = idx - b * HHU;
    const float* zr = z + (size_t)b * FOURHU;
    float hi = zr[u];
    float hf = zr[HHU + u];
    float hg = zr[2 * HHU + u];
    float ho = zr[3 * HHU + u];
    float c = sigf(hf) * hyper_c[idx] + sigf(hi) * tanhf(hg);
    hyper_c_new[idx] = c;
    float out = sigf(ho) * tanhf(c);
    hyper_out[idx] = out;
    bf16 h = __float2bfloat16(out);
    hoh[idx] = h;
    hol[idx] = __float2bfloat16(out - __bfloat162float(h));
}

// ---------------------------------------------------------------------------
// main epilogue
// ---------------------------------------------------------------------------
__device__ __forceinline__ void block_reduce2(float& a, float& b, float* sm)
{
    __syncthreads();
    #pragma unroll
    for (int o = 16; o > 0; o >>= 1) {
        a += __shfl_down_sync(0xffffffffu, a, o);
        b += __shfl_down_sync(0xffffffffu, b, o);
    }
    int w = threadIdx.x >> 5, l = threadIdx.x & 31;
    if (l == 0) { sm[w] = a; sm[32 + w] = b; }
    __syncthreads();
    if (w == 0) {
        int nw = blockDim.x >> 5;
        a = (l < nw) ? sm[l] : 0.0f;
        b = (l < nw) ? sm[32 + l] : 0.0f;
        #pragma unroll
        for (int o = 16; o > 0; o >>= 1) {
            a += __shfl_down_sync(0xffffffffu, a, o);
            b += __shfl_down_sync(0xffffffffu, b, o);
        }
        if (l == 0) { sm[0] = a; sm[32] = b; }
    }
    __syncthreads();
    a = sm[0];
    b = sm[32];
}

__global__ __launch_bounds__(512)
void main_epilogue(const float* __restrict__ dx, const float* __restrict__ dh,
                   const float* __restrict__ dbv, const float* __restrict__ px,
                   const float* __restrict__ ph, const float* __restrict__ main_c,
                   float* __restrict__ out_h, float* __restrict__ out_c)
{
    __shared__ float sm[64];
    const int b = blockIdx.x;
    const int t = threadIdx.x;
    const size_t base = (size_t)b * FOURU;

    float s[8];
    float sum = 0.0f, sq = 0.0f;
    #pragma unroll
    for (int r = 0; r < 8; r++) {
        int j = t + r * 512;
        float v = fmaf(dx[base + j], px[base + j],
                  fmaf(dh[base + j], ph[base + j], dbv[base + j]));
        s[r] = v;
        sum += v;
        sq = fmaf(v, v, sq);
    }
    block_reduce2(sum, sq, sm);
    float mean = sum * (1.0f / 4096.0f);
    float var = sq * (1.0f / 4096.0f) - mean * mean;
    float inv = rsqrtf(var + 1e-3f);

    float i0 = (s[0] - mean) * inv, i1 = (s[1] - mean) * inv;
    float f0 = (s[2] - mean) * inv, f1 = (s[3] - mean) * inv;
    float g0 = (s[4] - mean) * inv, g1 = (s[5] - mean) * inv;
    float o0 = (s[6] - mean) * inv, o1 = (s[7] - mean) * inv;

    const size_t cb = (size_t)b * UU;
    float c0 = sigf(f0) * main_c[cb + t]       + sigf(i0) * tanhf(g0);
    float c1 = sigf(f1) * main_c[cb + t + 512] + sigf(i1) * tanhf(g1);

    float sum2 = c0 + c1;
    float sq2 = fmaf(c0, c0, c1 * c1);
    block_reduce2(sum2, sq2, sm);
    float mean2 = sum2 * (1.0f / 1024.0f);
    float var2 = sq2 * (1.0f / 1024.0f) - mean2 * mean2;
    float inv2 = rsqrtf(var2 + 1e-3f);

    float h0 = sigf(o0) * tanhf((c0 - mean2) * inv2);
    float h1 = sigf(o1) * tanhf((c1 - mean2) * inv2);

    out_c[cb + t] = c0;
    out_c[cb + t + 512] = c1;
    out_h[cb + t] = h0;
    out_h[cb + t + 512] = h1;
}

// ---------------------------------------------------------------------------
// launch
// ---------------------------------------------------------------------------
extern "C" void kernel_launch(void* const* d_in, const int* in_sizes, int n_in,
                              void* d_out, int out_size)
{
    const float* inputs       = (const float*)d_in[0];
    const float* main_h       = (const float*)d_in[1];
    const float* main_c       = (const float*)d_in[2];
    const float* hyper_h      = (const float*)d_in[3];
    const float* hyper_c      = (const float*)d_in[4];
    const float* kernel_w     = (const float*)d_in[5];
    const float* rec_w        = (const float*)d_in[6];
    const float* bias         = (const float*)d_in[7];
    const float* hyper_kernel = (const float*)d_in[8];
    const float* hyper_rec    = (const float*)d_in[9];
    const float* hyper_bias   = (const float*)d_in[10];
    const float* dx_w         = (const float*)d_in[11];
    const float* dx_b         = (const float*)d_in[12];
    const float* dh_w         = (const float*)d_in[13];
    const float* dh_b         = (const float*)d_in[14];
    const float* db_w         = (const float*)d_in[15];
    const float* db_b         = (const float*)d_in[16];

    float* out = (float*)d_out;
    float* out_h  = out;
    float* out_c  = out + (size_t)BB * UU;
    float* out_ho = out + (size_t)2 * BB * UU;
    float* out_hc = out_ho + (size_t)BB * HHU;

    float *z, *dx, *dh, *db_, *px, *phv;
    cudaGetSymbolAddress((void**)&z,   g_z);
    cudaGetSymbolAddress((void**)&dx,  g_dx);
    cudaGetSymbolAddress((void**)&dh,  g_dh);
    cudaGetSymbolAddress((void**)&db_, g_db);
    cudaGetSymbolAddress((void**)&px,  g_px);
    cudaGetSymbolAddress((void**)&phv, g_ph);

    bf16 *ahyp_h, *ahyp_l, *aho_h, *aho_l;
    bf16 *wthyp_h, *wthyp_l, *wtdx_h, *wtdx_l, *wtdh_h, *wtdh_l, *wtdb_h, *wtdb_l;
    bf16 *wtk_h, *wtk_l, *wtr_h, *wtr_l;
    cudaGetSymbolAddress((void**)&ahyp_h, g_ahyp_h);
    cudaGetSymbolAddress((void**)&ahyp_l, g_ahyp_l);
    cudaGetSymbolAddress((void**)&aho_h,  g_aho_h);
    cudaGetSymbolAddress((void**)&aho_l,  g_aho_l);
    cudaGetSymbolAddress((void**)&wthyp_h, g_wthyp_h);
    cudaGetSymbolAddress((void**)&wthyp_l, g_wthyp_l);
    cudaGetSymbolAddress((void**)&wtdx_h, g_wtdx_h);
    cudaGetSymbolAddress((void**)&wtdx_l, g_wtdx_l);
    cudaGetSymbolAddress((void**)&wtdh_h, g_wtdh_h);
    cudaGetSymbolAddress((void**)&wtdh_l, g_wtdh_l);
    cudaGetSymbolAddress((void**)&wtdb_h, g_wtdb_h);
    cudaGetSymbolAddress((void**)&wtdb_l, g_wtdb_l);
    cudaGetSymbolAddress((void**)&wtk_h, g_wtk_h);
    cudaGetSymbolAddress((void**)&wtk_l, g_wtk_l);
    cudaGetSymbolAddress((void**)&wtr_h, g_wtr_h);
    cudaGetSymbolAddress((void**)&wtr_l, g_wtr_l);

    cudaFuncSetAttribute(gemm_mma, cudaFuncAttributeMaxDynamicSharedMemorySize, GEMM_SMEM);

    // ---- prep ----
    concat_split<<<(BB * KHYP / 4 + 255) / 256, 256>>>(inputs, main_h, hyper_h, ahyp_h, ahyp_l);

    dim3 tb(32, 8);
    trans_split<<<dim3(FOURHU/32, (DD+UU)/32), tb>>>(hyper_kernel, wthyp_h, wthyp_l, DD+UU, FOURHU, KHYP, 0);
    trans_split<<<dim3(FOURHU/32, HHU/32),     tb>>>(hyper_rec,    wthyp_h, wthyp_l, HHU,   FOURHU, KHYP, DD+UU);
    trans_split<<<dim3(FOURU/32,  HHU/32),     tb>>>(dx_w, wtdx_h, wtdx_l, HHU, FOURU, HHU, 0);
    trans_split<<<dim3(FOURU/32,  HHU/32),     tb>>>(dh_w, wtdh_h, wtdh_l, HHU, FOURU, HHU, 0);
    trans_split<<<dim3(FOURU/32,  HHU/32),     tb>>>(db_w, wtdb_h, wtdb_l, HHU, FOURU, HHU, 0);
    trans_split<<<dim3(FOURU/32,  UU/32),      tb>>>(kernel_w, wtk_h, wtk_l, UU, FOURU, UU, 0);
    trans_split<<<dim3(FOURU/32,  UU/32),      tb>>>(rec_w,    wtr_h, wtr_l, UU, FOURU, UU, 0);

    // ---- hyper GEMM: z = [inputs|main_h|hyper_h] @ wthyp^T + hyper_bias ----
    gemm_mma<<<dim3(FOURHU/128, BB/128), 256, GEMM_SMEM>>>(
        ahyp_h, ahyp_l, KHYP, wthyp_h, wthyp_l, KHYP, hyper_bias, z, FOURHU, KHYP);

    // ---- hyper pointwise ----
    hyper_pointwise<<<(BB * HHU + 255) / 256, 256>>>(z, hyper_c, out_ho, out_hc, aho_h, aho_l);

    // ---- hypernet scaling GEMMs (K=256) ----
    dim3 gbig(FOURU/128, BB/128);
    gemm_mma<<<gbig, 256, GEMM_SMEM>>>(aho_h, aho_l, HHU, wtdx_h, wtdx_l, HHU, dx_b, dx,  FOURU, HHU);
    gemm_mma<<<gbig, 256, GEMM_SMEM>>>(aho_h, aho_l, HHU, wtdh_h, wtdh_l, HHU, dh_b, dh,  FOURU, HHU);
    gemm_mma<<<gbig, 256, GEMM_SMEM>>>(aho_h, aho_l, HHU, wtdb_h, wtdb_l, HHU, db_b, db_, FOURU, HHU);

    // ---- main projections (K=1024) ----
    gemm_mma<<<gbig, 256, GEMM_SMEM>>>(ahyp_h,      ahyp_l,      KHYP, wtk_h, wtk_l, UU, bias,    px,  FOURU, UU);
    gemm_mma<<<gbig, 256, GEMM_SMEM>>>(ahyp_h + DD, ahyp_l + DD, KHYP, wtr_h, wtr_l, UU, nullptr, phv, FOURU, UU);

    // ---- fused LN + LSTM epilogue ----
    main_epilogue<<<BB, 512>>>(dx, dh, db_, px, phv, main_c, out_h, out_c);
}

// round 4
// speedup vs baseline: 3.5939x; 1.5742x over previous
#include <cuda_runtime.h>
#include <cuda_fp16.h>
#include <math.h>
#include <cstdint>

#define BB 2048
#define DD 1024
#define UU 1024
#define HHU 256
#define FOURU (4*UU)     // 4096
#define FOURHU (4*HHU)   // 1024
#define KHYP (DD+UU+HHU) // 2304

// ---------------------------------------------------------------------------
// scratch (static device arrays; no allocation allowed)
// ---------------------------------------------------------------------------
__device__ float g_z [BB * FOURHU];
__device__ float g_dx[BB * FOURU];
__device__ float g_dh[BB * FOURU];
__device__ float g_db[BB * FOURU];
__device__ float g_px[BB * FOURU];
__device__ float g_ph[BB * FOURU];

// fp16 split activations: [inputs | main_h | hyper_h] -> [2048, 2304]
__device__ __half g_ahyp_h[BB * KHYP];
__device__ __half g_ahyp_l[BB * KHYP];
__device__ __half g_aho_h[BB * HHU];
__device__ __half g_aho_l[BB * HHU];
// transposed fp16 weights ([N, K] row-major, k-contiguous), hi part only
__device__ __half g_wthyp[FOURHU * KHYP];
__device__ __half g_wtdx[FOURU * HHU];
__device__ __half g_wtdh[FOURU * HHU];
__device__ __half g_wtdb[FOURU * HHU];
__device__ __half g_wtk[FOURU * UU];
__device__ __half g_wtr[FOURU * UU];

__device__ __forceinline__ float sigf(float x) { return 1.0f / (1.0f + expf(-x)); }

__device__ __forceinline__ uint32_t smem_u32(const void* p) {
    uint32_t a;
    asm("{ .reg .u64 t; cvta.to.shared.u64 t, %1; cvt.u32.u64 %0, t; }" : "=r"(a) : "l"(p));
    return a;
}
__device__ __forceinline__ void cpa16(uint32_t dst, const void* src) {
    asm volatile("cp.async.cg.shared.global [%0], [%1], 16;" :: "r"(dst), "l"(src));
}
#define CP_COMMIT() asm volatile("cp.async.commit_group;" ::: "memory")
#define CP_WAIT(n)  asm volatile("cp.async.wait_group %0;" :: "n"(n) : "memory")

__device__ __forceinline__ void ldsm4(uint32_t* r, uint32_t addr) {
    asm volatile("ldmatrix.sync.aligned.m8n8.x4.shared.b16 {%0,%1,%2,%3}, [%4];"
                 : "=r"(r[0]), "=r"(r[1]), "=r"(r[2]), "=r"(r[3]) : "r"(addr));
}
__device__ __forceinline__ void mma_f16(float* c, const uint32_t* a, uint32_t b0, uint32_t b1) {
    asm volatile("mma.sync.aligned.m16n8k16.row.col.f32.f16.f16.f32 "
                 "{%0,%1,%2,%3}, {%4,%5,%6,%7}, {%8,%9}, {%0,%1,%2,%3};"
                 : "+f"(c[0]), "+f"(c[1]), "+f"(c[2]), "+f"(c[3])
                 : "r"(a[0]), "r"(a[1]), "r"(a[2]), "r"(a[3]), "r"(b0), "r"(b1));
}

// ---------------------------------------------------------------------------
// fp16 2-term GEMM: C[M,N] = (Ah+Al)[M,K] @ Wh[N,K]^T (+bias)
// CTA tile 128 x (64*WN); warps 2(m) x WN(n), warp tile 64x64; BK=64,
// 2-stage cp.async pipeline; smem rows padded to 144B (conflict-free ldmatrix).
// ---------------------------------------------------------------------------
#define SROW 144

template<int WN>
__global__ __launch_bounds__(64*WN, WN == 2 ? 2 : 1)
void gemm_f16(const __half* __restrict__ Ah, const __half* __restrict__ Al, int lda,
              const __half* __restrict__ Wh, int ldw,
              const float* __restrict__ bias, float* __restrict__ C,
              int N, int K)
{
    constexpr int NT      = 64 * WN;
    constexpr int THREADS = 64 * WN;
    constexpr int RP      = THREADS / 8;        // rows per load pass
    constexpr int A_BYTES = 128 * SROW;         // 18432
    constexpr int W_OFF   = 2 * A_BYTES;
    constexpr int SSZ     = (256 + NT) * SROW;  // stage bytes

    extern __shared__ char smem[];
    const uint32_t sb = smem_u32(smem);
    const int tid  = threadIdx.x;
    const int lane = tid & 31;
    const int wid  = tid >> 5;
    const int warp_m = wid & 1;
    const int warp_n = wid >> 1;
    const int m0 = blockIdx.y * 128;
    const int n0 = blockIdx.x * NT;

    const __half* pAh = Ah + (size_t)m0 * lda;
    const __half* pAl = Al + (size_t)m0 * lda;
    const __half* pWh = Wh + (size_t)n0 * ldw;

    float acc[4][8][4];
    #pragma unroll
    for (int a = 0; a < 4; a++)
        #pragma unroll
        for (int b = 0; b < 8; b++)
            #pragma unroll
            for (int c = 0; c < 4; c++) acc[a][b][c] = 0.0f;

    const uint32_t fr  = lane & 15;
    const uint32_t fcb = (lane >> 4) * 16;

    const int lr = tid >> 3;        // 0..RP-1
    const int lc = tid & 7;         // 16B chunk in row

    const int nch = K / 64;

    // stage loader
    auto load_stage = [&](uint32_t base, int k0) {
        #pragma unroll
        for (int i = 0; i < 128 / RP; i++) {
            int row = lr + i * RP;
            cpa16(base + row * SROW + lc * 16,           pAh + (size_t)row * lda + k0 + lc * 8);
            cpa16(base + A_BYTES + row * SROW + lc * 16, pAl + (size_t)row * lda + k0 + lc * 8);
        }
        #pragma unroll
        for (int i = 0; i < NT / RP; i++) {
            int row = lr + i * RP;
            cpa16(base + W_OFF + row * SROW + lc * 16,   pWh + (size_t)row * ldw + k0 + lc * 8);
        }
    };

    load_stage(sb, 0);
    CP_COMMIT();

    for (int kc = 0; kc < nch; kc++) {
        if (kc + 1 < nch) {
            load_stage(sb + ((kc + 1) & 1) * SSZ, (kc + 1) * 64);
            CP_COMMIT();
            CP_WAIT(1);
        } else {
            CP_WAIT(0);
        }
        __syncthreads();

        const uint32_t stg = sb + (kc & 1) * SSZ;
        #pragma unroll
        for (int s = 0; s < 4; s++) {
            const uint32_t kb = s * 32 + fcb;
            uint32_t ah[4][4], al[4][4];
            #pragma unroll
            for (int mt = 0; mt < 4; mt++) {
                uint32_t ra = stg + (warp_m * 64 + mt * 16 + fr) * SROW + kb;
                ldsm4(ah[mt], ra);
                ldsm4(al[mt], ra + A_BYTES);
            }
            #pragma unroll
            for (int np = 0; np < 4; np++) {
                uint32_t w[4];
                uint32_t rw = stg + W_OFF + (warp_n * 64 + np * 16 + fr) * SROW + kb;
                ldsm4(w, rw);
                #pragma unroll
                for (int mt = 0; mt < 4; mt++) {
                    mma_f16(acc[mt][2*np],   ah[mt], w[0], w[2]);
                    mma_f16(acc[mt][2*np],   al[mt], w[0], w[2]);
                    mma_f16(acc[mt][2*np+1], ah[mt], w[1], w[3]);
                    mma_f16(acc[mt][2*np+1], al[mt], w[1], w[3]);
                }
            }
        }
        __syncthreads();
    }

    // epilogue
    const int er = lane >> 2;
    const int ec = (lane & 3) * 2;
    #pragma unroll
    for (int mt = 0; mt < 4; mt++) {
        const int row = m0 + warp_m * 64 + mt * 16 + er;
        #pragma unroll
        for (int nt = 0; nt < 8; nt++) {
            const int col = n0 + warp_n * 64 + nt * 8 + ec;
            float b0 = 0.f, b1 = 0.f;
            if (bias) { b0 = bias[col]; b1 = bias[col + 1]; }
            *(float2*)(C + (size_t)row * N + col) =
                make_float2(acc[mt][nt][0] + b0, acc[mt][nt][1] + b1);
            *(float2*)(C + (size_t)(row + 8) * N + col) =
                make_float2(acc[mt][nt][2] + b0, acc[mt][nt][3] + b1);
        }
    }
}

// ---------------------------------------------------------------------------
// prep: concat + fp16-split activations -> [2048, 2304] h/l
// ---------------------------------------------------------------------------
__global__ void concat_split(const float* __restrict__ inputs,
                             const float* __restrict__ main_h,
                             const float* __restrict__ hyper_h,
                             __half* __restrict__ Dh, __half* __restrict__ Dl)
{
    int i4 = blockIdx.x * blockDim.x + threadIdx.x;
    if (i4 >= BB * KHYP / 4) return;
    int row = i4 / (KHYP / 4);
    int c4  = (i4 - row * (KHYP / 4)) * 4;
    const float* src;
    if (c4 < DD)            src = inputs  + (size_t)row * DD  + c4;
    else if (c4 < DD + UU)  src = main_h  + (size_t)row * UU  + (c4 - DD);
    else                    src = hyper_h + (size_t)row * HHU + (c4 - DD - UU);
    float4 v = *(const float4*)src;
    size_t o = (size_t)row * KHYP + c4;
    float a[4] = {v.x, v.y, v.z, v.w};
    ushort2 hs[2], ls[2];
    #pragma unroll
    for (int j = 0; j < 4; j++) {
        __half h = __float2half_rn(a[j]);
        __half l = __float2half_rn(a[j] - __half2float(h));
        ((unsigned short*)hs)[j] = __half_as_ushort(h);
        ((unsigned short*)ls)[j] = __half_as_ushort(l);
    }
    *(ushort2*)(Dh + o)     = hs[0];
    *(ushort2*)(Dh + o + 2) = hs[1];
    *(ushort2*)(Dl + o)     = ls[0];
    *(ushort2*)(Dl + o + 2) = ls[1];
}

// ---------------------------------------------------------------------------
// prep: transpose weight W[K,N] -> Th [N, dstLd] fp16 at column kOff
// 64(k) x 32(n) tiles; packed u32 stores along K.
// ---------------------------------------------------------------------------
__global__ void trans_w(const float* __restrict__ W, __half* __restrict__ Th,
                        int K, int N, int dstLd, int kOff)
{
    __shared__ float t[64][33];
    const int n0 = blockIdx.x * 32, k0 = blockIdx.y * 64;
    const int tx = threadIdx.x, ty = threadIdx.y;   // 32 x 8
    #pragma unroll
    for (int i = 0; i < 8; i++)
        t[ty + i * 8][tx] = W[(size_t)(k0 + ty + i * 8) * N + n0 + tx];
    __syncthreads();
    #pragma unroll
    for (int j = 0; j < 4; j++) {
        int n = ty + j * 8;
        float v0 = t[tx * 2][n], v1 = t[tx * 2 + 1][n];
        uint32_t pk = (uint32_t)__half_as_ushort(__float2half_rn(v0))
                    | ((uint32_t)__half_as_ushort(__float2half_rn(v1)) << 16);
        *(uint32_t*)(Th + (size_t)(n0 + n) * dstLd + kOff + k0 + tx * 2) = pk;
    }
}

// ---------------------------------------------------------------------------
// hyper LSTM pointwise (+ fp16 split of hyper_out)
// ---------------------------------------------------------------------------
__global__ void hyper_pointwise(const float* __restrict__ z,
                                const float* __restrict__ hyper_c,
                                float* __restrict__ hyper_out,
                                float* __restrict__ hyper_c_new,
                                __half* __restrict__ hoh, __half* __restrict__ hol)
{
    int idx = blockIdx.x * blockDim.x + threadIdx.x;
    if (idx >= BB * HHU) return;
    int b = idx / HHU;
    int u = idx - b * HHU;
    const float* zr = z + (size_t)b * FOURHU;
    float hi = zr[u];
    float hf = zr[HHU + u];
    float hg = zr[2 * HHU + u];
    float ho = zr[3 * HHU + u];
    float c = sigf(hf) * hyper_c[idx] + sigf(hi) * tanhf(hg);
    hyper_c_new[idx] = c;
    float out = sigf(ho) * tanhf(c);
    hyper_out[idx] = out;
    __half h = __float2half_rn(out);
    hoh[idx] = h;
    hol[idx] = __float2half_rn(out - __half2float(h));
}

// ---------------------------------------------------------------------------
// main epilogue
// ---------------------------------------------------------------------------
__device__ __forceinline__ void block_reduce2(float& a, float& b, float* sm)
{
    __syncthreads();
    #pragma unroll
    for (int o = 16; o > 0; o >>= 1) {
        a += __shfl_down_sync(0xffffffffu, a, o);
        b += __shfl_down_sync(0xffffffffu, b, o);
    }
    int w = threadIdx.x >> 5, l = threadIdx.x & 31;
    if (l == 0) { sm[w] = a; sm[32 + w] = b; }
    __syncthreads();
    if (w == 0) {
        int nw = blockDim.x >> 5;
        a = (l < nw) ? sm[l] : 0.0f;
        b = (l < nw) ? sm[32 + l] : 0.0f;
        #pragma unroll
        for (int o = 16; o > 0; o >>= 1) {
            a += __shfl_down_sync(0xffffffffu, a, o);
            b += __shfl_down_sync(0xffffffffu, b, o);
        }
        if (l == 0) { sm[0] = a; sm[32] = b; }
    }
    __syncthreads();
    a = sm[0];
    b = sm[32];
}

__global__ __launch_bounds__(512)
void main_epilogue(const float* __restrict__ dx, const float* __restrict__ dh,
                   const float* __restrict__ dbv, const float* __restrict__ px,
                   const float* __restrict__ ph, const float* __restrict__ main_c,
                   float* __restrict__ out_h, float* __restrict__ out_c)
{
    __shared__ float sm[64];
    const int b = blockIdx.x;
    const int t = threadIdx.x;
    const size_t base = (size_t)b * FOURU;

    float s[8];
    float sum = 0.0f, sq = 0.0f;
    #pragma unroll
    for (int r = 0; r < 8; r++) {
        int j = t + r * 512;
        float v = fmaf(dx[base + j], px[base + j],
                  fmaf(dh[base + j], ph[base + j], dbv[base + j]));
        s[r] = v;
        sum += v;
        sq = fmaf(v, v, sq);
    }
    block_reduce2(sum, sq, sm);
    float mean = sum * (1.0f / 4096.0f);
    float var = sq * (1.0f / 4096.0f) - mean * mean;
    float inv = rsqrtf(var + 1e-3f);

    float i0 = (s[0] - mean) * inv, i1 = (s[1] - mean) * inv;
    float f0 = (s[2] - mean) * inv, f1 = (s[3] - mean) * inv;
    float g0 = (s[4] - mean) * inv, g1 = (s[5] - mean) * inv;
    float o0 = (s[6] - mean) * inv, o1 = (s[7] - mean) * inv;

    const size_t cb = (size_t)b * UU;
    float c0 = sigf(f0) * main_c[cb + t]       + sigf(i0) * tanhf(g0);
    float c1 = sigf(f1) * main_c[cb + t + 512] + sigf(i1) * tanhf(g1);

    float sum2 = c0 + c1;
    float sq2 = fmaf(c0, c0, c1 * c1);
    block_reduce2(sum2, sq2, sm);
    float mean2 = sum2 * (1.0f / 1024.0f);
    float var2 = sq2 * (1.0f / 1024.0f) - mean2 * mean2;
    float inv2 = rsqrtf(var2 + 1e-3f);

    float h0 = sigf(o0) * tanhf((c0 - mean2) * inv2);
    float h1 = sigf(o1) * tanhf((c1 - mean2) * inv2);

    out_c[cb + t] = c0;
    out_c[cb + t + 512] = c1;
    out_h[cb + t] = h0;
    out_h[cb + t + 512] = h1;
}

// ---------------------------------------------------------------------------
// launch
// ---------------------------------------------------------------------------
extern "C" void kernel_launch(void* const* d_in, const int* in_sizes, int n_in,
                              void* d_out, int out_size)
{
    const float* inputs       = (const float*)d_in[0];
    const float* main_h       = (const float*)d_in[1];
    const float* main_c       = (const float*)d_in[2];
    const float* hyper_h      = (const float*)d_in[3];
    const float* hyper_c      = (const float*)d_in[4];
    const float* kernel_w     = (const float*)d_in[5];
    const float* rec_w        = (const float*)d_in[6];
    const float* bias         = (const float*)d_in[7];
    const float* hyper_kernel = (const float*)d_in[8];
    const float* hyper_rec    = (const float*)d_in[9];
    const float* hyper_bias   = (const float*)d_in[10];
    const float* dx_w         = (const float*)d_in[11];
    const float* dx_b         = (const float*)d_in[12];
    const float* dh_w         = (const float*)d_in[13];
    const float* dh_b         = (const float*)d_in[14];
    const float* db_w         = (const float*)d_in[15];
    const float* db_b         = (const float*)d_in[16];

    float* out = (float*)d_out;
    float* out_h  = out;
    float* out_c  = out + (size_t)BB * UU;
    float* out_ho = out + (size_t)2 * BB * UU;
    float* out_hc = out_ho + (size_t)BB * HHU;

    float *z, *dx, *dh, *db_, *px, *phv;
    cudaGetSymbolAddress((void**)&z,   g_z);
    cudaGetSymbolAddress((void**)&dx,  g_dx);
    cudaGetSymbolAddress((void**)&dh,  g_dh);
    cudaGetSymbolAddress((void**)&db_, g_db);
    cudaGetSymbolAddress((void**)&px,  g_px);
    cudaGetSymbolAddress((void**)&phv, g_ph);

    __half *ahyp_h, *ahyp_l, *aho_h, *aho_l;
    __half *wthyp, *wtdx, *wtdh, *wtdb, *wtk, *wtr;
    cudaGetSymbolAddress((void**)&ahyp_h, g_ahyp_h);
    cudaGetSymbolAddress((void**)&ahyp_l, g_ahyp_l);
    cudaGetSymbolAddress((void**)&aho_h,  g_aho_h);
    cudaGetSymbolAddress((void**)&aho_l,  g_aho_l);
    cudaGetSymbolAddress((void**)&wthyp,  g_wthyp);
    cudaGetSymbolAddress((void**)&wtdx,   g_wtdx);
    cudaGetSymbolAddress((void**)&wtdh,   g_wtdh);
    cudaGetSymbolAddress((void**)&wtdb,   g_wtdb);
    cudaGetSymbolAddress((void**)&wtk,    g_wtk);
    cudaGetSymbolAddress((void**)&wtr,    g_wtr);

    constexpr int SSZ4 = (256 + 256) * SROW;   // 73728
    constexpr int SSZ2 = (256 + 128) * SROW;   // 55296
    cudaFuncSetAttribute(gemm_f16<4>, cudaFuncAttributeMaxDynamicSharedMemorySize, 2 * SSZ4);
    cudaFuncSetAttribute(gemm_f16<2>, cudaFuncAttributeMaxDynamicSharedMemorySize, 2 * SSZ2);

    // ---- prep ----
    concat_split<<<(BB * KHYP / 4 + 255) / 256, 256>>>(inputs, main_h, hyper_h, ahyp_h, ahyp_l);

    dim3 tb(32, 8);
    trans_w<<<dim3(FOURHU/32, (DD+UU)/64), tb>>>(hyper_kernel, wthyp, DD+UU, FOURHU, KHYP, 0);
    trans_w<<<dim3(FOURHU/32, HHU/64),     tb>>>(hyper_rec,    wthyp, HHU,   FOURHU, KHYP, DD+UU);
    trans_w<<<dim3(FOURU/32,  HHU/64),     tb>>>(dx_w, wtdx, HHU, FOURU, HHU, 0);
    trans_w<<<dim3(FOURU/32,  HHU/64),     tb>>>(dh_w, wtdh, HHU, FOURU, HHU, 0);
    trans_w<<<dim3(FOURU/32,  HHU/64),     tb>>>(db_w, wtdb, HHU, FOURU, HHU, 0);
    trans_w<<<dim3(FOURU/32,  UU/64),      tb>>>(kernel_w, wtk, UU, FOURU, UU, 0);
    trans_w<<<dim3(FOURU/32,  UU/64),      tb>>>(rec_w,    wtr, UU, FOURU, UU, 0);

    // ---- hyper GEMM: z = [inputs|main_h|hyper_h] @ wthyp^T + hyper_bias ----
    gemm_f16<2><<<dim3(FOURHU/128, BB/128), 128, 2*SSZ2>>>(
        ahyp_h, ahyp_l, KHYP, wthyp, KHYP, hyper_bias, z, FOURHU, KHYP);

    // ---- hyper pointwise ----
    hyper_pointwise<<<(BB * HHU + 255) / 256, 256>>>(z, hyper_c, out_ho, out_hc, aho_h, aho_l);

    // ---- hypernet scaling GEMMs (K=256) ----
    dim3 gbig(FOURU/256, BB/128);
    gemm_f16<4><<<gbig, 256, 2*SSZ4>>>(aho_h, aho_l, HHU, wtdx, HHU, dx_b, dx,  FOURU, HHU);
    gemm_f16<4><<<gbig, 256, 2*SSZ4>>>(aho_h, aho_l, HHU, wtdh, HHU, dh_b, dh,  FOURU, HHU);
    gemm_f16<4><<<gbig, 256, 2*SSZ4>>>(aho_h, aho_l, HHU, wtdb, HHU, db_b, db_, FOURU, HHU);

    // ---- main projections (K=1024) ----
    gemm_f16<4><<<gbig, 256, 2*SSZ4>>>(ahyp_h,      ahyp_l,      KHYP, wtk, UU, bias,    px,  FOURU, UU);
    gemm_f16<4><<<gbig, 256, 2*SSZ4>>>(ahyp_h + DD, ahyp_l + DD, KHYP, wtr, UU, nullptr, phv, FOURU, UU);

    // ---- fused LN + LSTM epilogue ----
    main_epilogue<<<BB, 512>>>(dx, dh, db_, px, phv, main_c, out_h, out_c);
}

// round 5
// speedup vs baseline: 5.0953x; 1.4177x over previous
#include <cuda_runtime.h>
#include <cuda_fp16.h>
#include <math.h>
#include <cstdint>

#define BB 2048
#define DD 1024
#define UU 1024
#define HHU 256
#define FOURU (4*UU)     // 4096
#define FOURHU (4*HHU)   // 1024
#define KHYP (DD+UU+HHU) // 2304
#define N3 (3*FOURU)     // 12288

// ---------------------------------------------------------------------------
// scratch (static device arrays; no allocation allowed)
// ---------------------------------------------------------------------------
__device__ float g_z  [BB * FOURHU];
__device__ float g_d3 [BB * N3];      // [2048, 12288] = dx | dh | db per row
__device__ float g_px [BB * FOURU];
__device__ float g_ph [BB * FOURU];
__device__ float g_ball[N3];          // packed dx_b | dh_b | db_b

// fp16 activations
__device__ __half g_ahyp_h[BB * KHYP];  // hi split of [inputs|main_h|hyper_h]
__device__ __half g_ahyp_l[BB * KHYP];  // lo split (hyper GEMM only)
__device__ __half g_aho   [BB * HHU];   // hyper_out fp16
// transposed fp16 weights ([N, K] row-major, k-contiguous)
__device__ __half g_wthyp[FOURHU * KHYP];
__device__ __half g_wtall[N3 * HHU];    // dx_w^T | dh_w^T | db_w^T stacked on N
__device__ __half g_wtk[FOURU * UU];
__device__ __half g_wtr[FOURU * UU];

__device__ __forceinline__ float sigf(float x) { return 1.0f / (1.0f + expf(-x)); }

__device__ __forceinline__ uint32_t smem_u32(const void* p) {
    uint32_t a;
    asm("{ .reg .u64 t; cvta.to.shared.u64 t, %1; cvt.u32.u64 %0, t; }" : "=r"(a) : "l"(p));
    return a;
}
__device__ __forceinline__ void cpa16(uint32_t dst, const void* src) {
    asm volatile("cp.async.cg.shared.global [%0], [%1], 16;" :: "r"(dst), "l"(src));
}
#define CP_COMMIT() asm volatile("cp.async.commit_group;" ::: "memory")
#define CP_WAIT(n)  asm volatile("cp.async.wait_group %0;" :: "n"(n) : "memory")

__device__ __forceinline__ void ldsm4(uint32_t* r, uint32_t addr) {
    asm volatile("ldmatrix.sync.aligned.m8n8.x4.shared.b16 {%0,%1,%2,%3}, [%4];"
                 : "=r"(r[0]), "=r"(r[1]), "=r"(r[2]), "=r"(r[3]) : "r"(addr));
}
__device__ __forceinline__ void mma_f16(float* c, const uint32_t* a, uint32_t b0, uint32_t b1) {
    asm volatile("mma.sync.aligned.m16n8k16.row.col.f32.f16.f16.f32 "
                 "{%0,%1,%2,%3}, {%4,%5,%6,%7}, {%8,%9}, {%0,%1,%2,%3};"
                 : "+f"(c[0]), "+f"(c[1]), "+f"(c[2]), "+f"(c[3])
                 : "r"(a[0]), "r"(a[1]), "r"(a[2]), "r"(a[3]), "r"(b0), "r"(b1));
}

// ---------------------------------------------------------------------------
// GEMM core: C[M,N] = (Ah [+Al]) [M,K] @ Wh[N,K]^T (+bias)
// CTA tile 128 x (64*WN); warps 2(m) x WN(n); warp tile 64x64; BK=64;
// 2-stage cp.async; smem rows 144B (conflict-free ldmatrix).
// ---------------------------------------------------------------------------
#define SROW 144

template<int WN, int TERMS>
__device__ __forceinline__
void gemm_core(const __half* __restrict__ Ah, const __half* __restrict__ Al, int lda,
               const __half* __restrict__ Wh, int ldw,
               const float* __restrict__ bias, float* __restrict__ C,
               int N, int K, char* smem)
{
    constexpr int NT      = 64 * WN;
    constexpr int THREADS = 64 * WN;
    constexpr int RP      = THREADS / 8;
    constexpr int A_BYTES = 128 * SROW;
    constexpr int W_OFF   = TERMS * A_BYTES;
    constexpr int SSZ     = (128 * TERMS + NT) * SROW;

    const uint32_t sb = smem_u32(smem);
    const int tid  = threadIdx.x;
    const int lane = tid & 31;
    const int wid  = tid >> 5;
    const int warp_m = wid & 1;
    const int warp_n = wid >> 1;
    const int m0 = blockIdx.y * 128;
    const int n0 = blockIdx.x * NT;

    const __half* pAh = Ah + (size_t)m0 * lda;
    const __half* pAl = (TERMS == 2) ? (Al + (size_t)m0 * lda) : nullptr;
    const __half* pWh = Wh + (size_t)n0 * ldw;

    float acc[4][8][4];
    #pragma unroll
    for (int a = 0; a < 4; a++)
        #pragma unroll
        for (int b = 0; b < 8; b++)
            #pragma unroll
            for (int c = 0; c < 4; c++) acc[a][b][c] = 0.0f;

    const uint32_t fr  = lane & 15;
    const uint32_t fcb = (lane >> 4) * 16;
    const int lr = tid >> 3;
    const int lc = tid & 7;
    const int nch = K / 64;

    auto load_stage = [&](uint32_t base, int k0) {
        #pragma unroll
        for (int i = 0; i < 128 / RP; i++) {
            int row = lr + i * RP;
            cpa16(base + row * SROW + lc * 16, pAh + (size_t)row * lda + k0 + lc * 8);
            if (TERMS == 2)
                cpa16(base + A_BYTES + row * SROW + lc * 16,
                      pAl + (size_t)row * lda + k0 + lc * 8);
        }
        #pragma unroll
        for (int i = 0; i < NT / RP; i++) {
            int row = lr + i * RP;
            cpa16(base + W_OFF + row * SROW + lc * 16, pWh + (size_t)row * ldw + k0 + lc * 8);
        }
    };

    load_stage(sb, 0);
    CP_COMMIT();

    for (int kc = 0; kc < nch; kc++) {
        if (kc + 1 < nch) {
            load_stage(sb + ((kc + 1) & 1) * SSZ, (kc + 1) * 64);
            CP_COMMIT();
            CP_WAIT(1);
        } else {
            CP_WAIT(0);
        }
        __syncthreads();

        const uint32_t stg = sb + (kc & 1) * SSZ;
        #pragma unroll
        for (int s = 0; s < 4; s++) {
            const uint32_t kb = s * 32 + fcb;
            uint32_t ah[4][4], al[4][4];
            #pragma unroll
            for (int mt = 0; mt < 4; mt++) {
                uint32_t ra = stg + (warp_m * 64 + mt * 16 + fr) * SROW + kb;
                ldsm4(ah[mt], ra);
                if (TERMS == 2) ldsm4(al[mt], ra + A_BYTES);
            }
            #pragma unroll
            for (int np = 0; np < 4; np++) {
                uint32_t w[4];
                uint32_t rw = stg + W_OFF + (warp_n * 64 + np * 16 + fr) * SROW + kb;
                ldsm4(w, rw);
                #pragma unroll
                for (int mt = 0; mt < 4; mt++) {
                    mma_f16(acc[mt][2*np],   ah[mt], w[0], w[2]);
                    mma_f16(acc[mt][2*np+1], ah[mt], w[1], w[3]);
                    if (TERMS == 2) {
                        mma_f16(acc[mt][2*np],   al[mt], w[0], w[2]);
                        mma_f16(acc[mt][2*np+1], al[mt], w[1], w[3]);
                    }
                }
            }
        }
        __syncthreads();
    }

    const int er = lane >> 2;
    const int ec = (lane & 3) * 2;
    #pragma unroll
    for (int mt = 0; mt < 4; mt++) {
        const int row = m0 + warp_m * 64 + mt * 16 + er;
        #pragma unroll
        for (int nt = 0; nt < 8; nt++) {
            const int col = n0 + warp_n * 64 + nt * 8 + ec;
            float b0 = 0.f, b1 = 0.f;
            if (bias) { b0 = bias[col]; b1 = bias[col + 1]; }
            *(float2*)(C + (size_t)row * N + col) =
                make_float2(acc[mt][nt][0] + b0, acc[mt][nt][1] + b1);
            *(float2*)(C + (size_t)(row + 8) * N + col) =
                make_float2(acc[mt][nt][2] + b0, acc[mt][nt][3] + b1);
        }
    }
}

template<int WN, int TERMS>
__global__ __launch_bounds__(64*WN, 1)
void gemm_k(const __half* __restrict__ Ah, const __half* __restrict__ Al, int lda,
            const __half* __restrict__ Wh, int ldw,
            const float* __restrict__ bias, float* __restrict__ C, int N, int K)
{
    extern __shared__ char smem[];
    gemm_core<WN, TERMS>(Ah, Al, lda, Wh, ldw, bias, C, N, K, smem);
}

// px / ph in one launch: blockIdx.z selects the (A, W, bias, C) set.
__global__ __launch_bounds__(256, 1)
void gemm_pxph(const __half* __restrict__ A0, const __half* __restrict__ W0,
               const float* __restrict__ b0, float* __restrict__ C0,
               const __half* __restrict__ A1, const __half* __restrict__ W1,
               float* __restrict__ C1, int lda)
{
    extern __shared__ char smem[];
    if (blockIdx.z == 0)
        gemm_core<4, 1>(A0, nullptr, lda, W0, UU, b0,      C0, FOURU, UU, smem);
    else
        gemm_core<4, 1>(A1, nullptr, lda, W1, UU, nullptr, C1, FOURU, UU, smem);
}

// ---------------------------------------------------------------------------
// prep: concat + fp16-split activations -> [2048, 2304] h/l
// ---------------------------------------------------------------------------
__global__ void concat_split(const float* __restrict__ inputs,
                             const float* __restrict__ main_h,
                             const float* __restrict__ hyper_h,
                             __half* __restrict__ Dh, __half* __restrict__ Dl)
{
    int i4 = blockIdx.x * blockDim.x + threadIdx.x;
    if (i4 >= BB * KHYP / 4) return;
    int row = i4 / (KHYP / 4);
    int c4  = (i4 - row * (KHYP / 4)) * 4;
    const float* src;
    if (c4 < DD)            src = inputs  + (size_t)row * DD  + c4;
    else if (c4 < DD + UU)  src = main_h  + (size_t)row * UU  + (c4 - DD);
    else                    src = hyper_h + (size_t)row * HHU + (c4 - DD - UU);
    float4 v = *(const float4*)src;
    size_t o = (size_t)row * KHYP + c4;
    float a[4] = {v.x, v.y, v.z, v.w};
    unsigned short hs[4], ls[4];
    #pragma unroll
    for (int j = 0; j < 4; j++) {
        __half h = __float2half_rn(a[j]);
        hs[j] = __half_as_ushort(h);
        ls[j] = __half_as_ushort(__float2half_rn(a[j] - __half2float(h)));
    }
    *(uint2*)(Dh + o) = make_uint2((uint32_t)hs[0] | ((uint32_t)hs[1] << 16),
                                   (uint32_t)hs[2] | ((uint32_t)hs[3] << 16));
    *(uint2*)(Dl + o) = make_uint2((uint32_t)ls[0] | ((uint32_t)ls[1] << 16),
                                   (uint32_t)ls[2] | ((uint32_t)ls[3] << 16));
}

// ---------------------------------------------------------------------------
// prep: transpose weight W[K,N] -> Th [N, dstLd] fp16 at (rowOff, kOff).
// srcs/dsts selected by blockIdx.z.
// ---------------------------------------------------------------------------
__device__ __forceinline__ void trans_tile(const float* __restrict__ W,
                                           __half* __restrict__ Th,
                                           int N, int dstLd, int kOff,
                                           int n0, int k0)
{
    __shared__ float t[64][33];
    const int tx = threadIdx.x, ty = threadIdx.y;   // 32 x 8
    #pragma unroll
    for (int i = 0; i < 8; i++)
        t[ty + i * 8][tx] = W[(size_t)(k0 + ty + i * 8) * N + n0 + tx];
    __syncthreads();
    #pragma unroll
    for (int j = 0; j < 4; j++) {
        int n = ty + j * 8;
        float v0 = t[tx * 2][n], v1 = t[tx * 2 + 1][n];
        uint32_t pk = (uint32_t)__half_as_ushort(__float2half_rn(v0))
                    | ((uint32_t)__half_as_ushort(__float2half_rn(v1)) << 16);
        *(uint32_t*)(Th + (size_t)(n0 + n) * dstLd + kOff + k0 + tx * 2) = pk;
    }
}

// z in {0,1,2}: dx_w/dh_w/db_w [256,4096] -> g_wtall rows z*4096..
__global__ void trans_d3(const float* __restrict__ w0, const float* __restrict__ w1,
                         const float* __restrict__ w2, __half* __restrict__ Tall)
{
    const float* W = (blockIdx.z == 0) ? w0 : (blockIdx.z == 1) ? w1 : w2;
    trans_tile(W, Tall + (size_t)blockIdx.z * FOURU * HHU, FOURU, HHU, 0,
               blockIdx.x * 32, blockIdx.y * 64);
}

// z in {0,1}: kernel_w / rec_w [1024,4096] -> wtk / wtr
__global__ void trans_kr(const float* __restrict__ kw, const float* __restrict__ rw,
                         __half* __restrict__ Tk, __half* __restrict__ Tr)
{
    const float* W = blockIdx.z ? rw : kw;
    __half* T = blockIdx.z ? Tr : Tk;
    trans_tile(W, T, FOURU, UU, 0, blockIdx.x * 32, blockIdx.y * 64);
}

// hyper weights: z=0 hyper_kernel [2048,1024] (kOff 0), z=1 hyper_rec [256,1024]
__global__ void trans_hyp(const float* __restrict__ hk, const float* __restrict__ hr,
                          __half* __restrict__ T)
{
    if (blockIdx.z == 0) {
        trans_tile(hk, T, FOURHU, KHYP, 0, blockIdx.x * 32, blockIdx.y * 64);
    } else {
        if (blockIdx.y >= HHU / 64) return;
        trans_tile(hr, T, FOURHU, KHYP, DD + UU, blockIdx.x * 32, blockIdx.y * 64);
    }
}

// pack biases
__global__ void pack_bias(const float* __restrict__ b0, const float* __restrict__ b1,
                          const float* __restrict__ b2, float* __restrict__ out)
{
    int i = blockIdx.x * blockDim.x + threadIdx.x;
    if (i >= N3) return;
    out[i] = (i < FOURU) ? b0[i] : (i < 2*FOURU) ? b1[i - FOURU] : b2[i - 2*FOURU];
}

// ---------------------------------------------------------------------------
// hyper LSTM pointwise (+ fp16 of hyper_out)
// ---------------------------------------------------------------------------
__global__ void hyper_pointwise(const float* __restrict__ z,
                                const float* __restrict__ hyper_c,
                                float* __restrict__ hyper_out,
                                float* __restrict__ hyper_c_new,
                                __half* __restrict__ hoh)
{
    int idx = blockIdx.x * blockDim.x + threadIdx.x;
    if (idx >= BB * HHU) return;
    int b = idx / HHU;
    int u = idx - b * HHU;
    const float* zr = z + (size_t)b * FOURHU;
    float hi = zr[u];
    float hf = zr[HHU + u];
    float hg = zr[2 * HHU + u];
    float ho = zr[3 * HHU + u];
    float c = sigf(hf) * hyper_c[idx] + sigf(hi) * tanhf(hg);
    hyper_c_new[idx] = c;
    float out = sigf(ho) * tanhf(c);
    hyper_out[idx] = out;
    hoh[idx] = __float2half_rn(out);
}

// ---------------------------------------------------------------------------
// main epilogue (d3 packed: row stride 12288; dx|dh|db)
// ---------------------------------------------------------------------------
__device__ __forceinline__ void block_reduce2(float& a, float& b, float* sm)
{
    __syncthreads();
    #pragma unroll
    for (int o = 16; o > 0; o >>= 1) {
        a += __shfl_down_sync(0xffffffffu, a, o);
        b += __shfl_down_sync(0xffffffffu, b, o);
    }
    int w = threadIdx.x >> 5, l = threadIdx.x & 31;
    if (l == 0) { sm[w] = a; sm[32 + w] = b; }
    __syncthreads();
    if (w == 0) {
        int nw = blockDim.x >> 5;
        a = (l < nw) ? sm[l] : 0.0f;
        b = (l < nw) ? sm[32 + l] : 0.0f;
        #pragma unroll
        for (int o = 16; o > 0; o >>= 1) {
            a += __shfl_down_sync(0xffffffffu, a, o);
            b += __shfl_down_sync(0xffffffffu, b, o);
        }
        if (l == 0) { sm[0] = a; sm[32] = b; }
    }
    __syncthreads();
    a = sm[0];
    b = sm[32];
}

__global__ __launch_bounds__(512)
void main_epilogue(const float* __restrict__ d3, const float* __restrict__ px,
                   const float* __restrict__ ph, const float* __restrict__ main_c,
                   float* __restrict__ out_h, float* __restrict__ out_c)
{
    __shared__ float sm[64];
    const int b = blockIdx.x;
    const int t = threadIdx.x;
    const size_t b4 = (size_t)b * FOURU;
    const size_t b3 = (size_t)b * N3;

    float s[8];
    float sum = 0.0f, sq = 0.0f;
    #pragma unroll
    for (int r = 0; r < 8; r++) {
        int j = t + r * 512;
        float v = fmaf(d3[b3 + j], px[b4 + j],
                  fmaf(d3[b3 + FOURU + j], ph[b4 + j], d3[b3 + 2*FOURU + j]));
        s[r] = v;
        sum += v;
        sq = fmaf(v, v, sq);
    }
    block_reduce2(sum, sq, sm);
    float mean = sum * (1.0f / 4096.0f);
    float var = sq * (1.0f / 4096.0f) - mean * mean;
    float inv = rsqrtf(var + 1e-3f);

    float i0 = (s[0] - mean) * inv, i1 = (s[1] - mean) * inv;
    float f0 = (s[2] - mean) * inv, f1 = (s[3] - mean) * inv;
    float g0 = (s[4] - mean) * inv, g1 = (s[5] - mean) * inv;
    float o0 = (s[6] - mean) * inv, o1 = (s[7] - mean) * inv;

    const size_t cb = (size_t)b * UU;
    float c0 = sigf(f0) * main_c[cb + t]       + sigf(i0) * tanhf(g0);
    float c1 = sigf(f1) * main_c[cb + t + 512] + sigf(i1) * tanhf(g1);

    float sum2 = c0 + c1;
    float sq2 = fmaf(c0, c0, c1 * c1);
    block_reduce2(sum2, sq2, sm);
    float mean2 = sum2 * (1.0f / 1024.0f);
    float var2 = sq2 * (1.0f / 1024.0f) - mean2 * mean2;
    float inv2 = rsqrtf(var2 + 1e-3f);

    float h0 = sigf(o0) * tanhf((c0 - mean2) * inv2);
    float h1 = sigf(o1) * tanhf((c1 - mean2) * inv2);

    out_c[cb + t] = c0;
    out_c[cb + t + 512] = c1;
    out_h[cb + t] = h0;
    out_h[cb + t + 512] = h1;
}

// ---------------------------------------------------------------------------
// launch
// ---------------------------------------------------------------------------
extern "C" void kernel_launch(void* const* d_in, const int* in_sizes, int n_in,
                              void* d_out, int out_size)
{
    const float* inputs       = (const float*)d_in[0];
    const float* main_h       = (const float*)d_in[1];
    const float* main_c       = (const float*)d_in[2];
    const float* hyper_h      = (const float*)d_in[3];
    const float* hyper_c      = (const float*)d_in[4];
    const float* kernel_w     = (const float*)d_in[5];
    const float* rec_w        = (const float*)d_in[6];
    const float* bias         = (const float*)d_in[7];
    const float* hyper_kernel = (const float*)d_in[8];
    const float* hyper_rec    = (const float*)d_in[9];
    const float* hyper_bias   = (const float*)d_in[10];
    const float* dx_w         = (const float*)d_in[11];
    const float* dx_b         = (const float*)d_in[12];
    const float* dh_w         = (const float*)d_in[13];
    const float* dh_b         = (const float*)d_in[14];
    const float* db_w         = (const float*)d_in[15];
    const float* db_b         = (const float*)d_in[16];

    float* out = (float*)d_out;
    float* out_h  = out;
    float* out_c  = out + (size_t)BB * UU;
    float* out_ho = out + (size_t)2 * BB * UU;
    float* out_hc = out_ho + (size_t)BB * HHU;

    float *z, *d3, *px, *phv, *ball;
    cudaGetSymbolAddress((void**)&z,    g_z);
    cudaGetSymbolAddress((void**)&d3,   g_d3);
    cudaGetSymbolAddress((void**)&px,   g_px);
    cudaGetSymbolAddress((void**)&phv,  g_ph);
    cudaGetSymbolAddress((void**)&ball, g_ball);

    __half *ahyp_h, *ahyp_l, *aho;
    __half *wthyp, *wtall, *wtk, *wtr;
    cudaGetSymbolAddress((void**)&ahyp_h, g_ahyp_h);
    cudaGetSymbolAddress((void**)&ahyp_l, g_ahyp_l);
    cudaGetSymbolAddress((void**)&aho,    g_aho);
    cudaGetSymbolAddress((void**)&wthyp,  g_wthyp);
    cudaGetSymbolAddress((void**)&wtall,  g_wtall);
    cudaGetSymbolAddress((void**)&wtk,    g_wtk);
    cudaGetSymbolAddress((void**)&wtr,    g_wtr);

    constexpr int SSZ_H  = (256 + 128) * SROW;   // hyper: WN=2, TERMS=2
    constexpr int SSZ_1  = (128 + 256) * SROW;   // WN=4, TERMS=1
    cudaFuncSetAttribute(gemm_k<2,2>, cudaFuncAttributeMaxDynamicSharedMemorySize, 2 * SSZ_H);
    cudaFuncSetAttribute(gemm_k<4,1>, cudaFuncAttributeMaxDynamicSharedMemorySize, 2 * SSZ_1);
    cudaFuncSetAttribute(gemm_pxph,  cudaFuncAttributeMaxDynamicSharedMemorySize, 2 * SSZ_1);

    dim3 tb(32, 8);

    // ---- prep ----
    concat_split<<<(BB * KHYP / 4 + 255) / 256, 256>>>(inputs, main_h, hyper_h, ahyp_h, ahyp_l);
    trans_hyp<<<dim3(FOURHU/32, (DD+UU)/64, 2), tb>>>(hyper_kernel, hyper_rec, wthyp);
    trans_d3 <<<dim3(FOURU/32, HHU/64, 3), tb>>>(dx_w, dh_w, db_w, wtall);
    trans_kr <<<dim3(FOURU/32, UU/64, 2), tb>>>(kernel_w, rec_w, wtk, wtr);
    pack_bias<<<(N3 + 255) / 256, 256>>>(dx_b, dh_b, db_b, ball);

    // ---- hyper GEMM (2-term fp16): z = ahyp @ wthyp^T + hyper_bias ----
    gemm_k<2,2><<<dim3(FOURHU/128, BB/128), 128, 2*SSZ_H>>>(
        ahyp_h, ahyp_l, KHYP, wthyp, KHYP, hyper_bias, z, FOURHU, KHYP);

    // ---- hyper pointwise ----
    hyper_pointwise<<<(BB * HHU + 255) / 256, 256>>>(z, hyper_c, out_ho, out_hc, aho);

    // ---- fused d_x|d_h|d_b GEMM (1-term): [2048,256] @ [12288,256]^T ----
    gemm_k<4,1><<<dim3(N3/256, BB/128), 256, 2*SSZ_1>>>(
        aho, nullptr, HHU, wtall, HHU, ball, d3, N3, HHU);

    // ---- px & ph in one launch (1-term, K=1024) ----
    gemm_pxph<<<dim3(FOURU/256, BB/128, 2), 256, 2*SSZ_1>>>(
        ahyp_h, wtk, bias, px,
        ahyp_h + DD, wtr, phv, KHYP);

    // ---- fused LN + LSTM epilogue ----
    main_epilogue<<<BB, 512>>>(d3, px, phv, main_c, out_h, out_c);
}

// round 6
// speedup vs baseline: 5.8809x; 1.1542x over previous
#include <cuda_runtime.h>
#include <cuda_fp16.h>
#include <math.h>
#include <cstdint>

#define BB 2048
#define DD 1024
#define UU 1024
#define HHU 256
#define FOURU (4*UU)     // 4096
#define FOURHU (4*HHU)   // 1024
#define KHYP (DD+UU+HHU) // 2304
#define N3 (3*FOURU)     // 12288

// ---------------------------------------------------------------------------
// scratch (static device arrays; no allocation allowed)
// ---------------------------------------------------------------------------
__device__ float g_z [BB * FOURHU];
__device__ float g_s [BB * FOURU];    // fused gate pre-activations
__device__ float g_px[BB * FOURU];
__device__ float g_ph[BB * FOURU];

// fp16 activations
__device__ __half g_ahyp[BB * KHYP];   // fp16 of [inputs|main_h|hyper_h]
__device__ __half g_aho [BB * HHU];    // fp16 of hyper_out
// transposed fp16 weights ([N, K] row-major, k-contiguous)
__device__ __half g_wthyp[FOURHU * KHYP];
__device__ __half g_wtall[N3 * HHU];   // dx_w^T | dh_w^T | db_w^T stacked on N
__device__ __half g_wtk[FOURU * UU];
__device__ __half g_wtr[FOURU * UU];

__device__ __forceinline__ float sigf(float x) { return 1.0f / (1.0f + expf(-x)); }

__device__ __forceinline__ uint32_t smem_u32(const void* p) {
    uint32_t a;
    asm("{ .reg .u64 t; cvta.to.shared.u64 t, %1; cvt.u32.u64 %0, t; }" : "=r"(a) : "l"(p));
    return a;
}
__device__ __forceinline__ void cpa16(uint32_t dst, const void* src) {
    asm volatile("cp.async.cg.shared.global [%0], [%1], 16;" :: "r"(dst), "l"(src));
}
#define CP_COMMIT() asm volatile("cp.async.commit_group;" ::: "memory")
#define CP_WAIT(n)  asm volatile("cp.async.wait_group %0;" :: "n"(n) : "memory")

__device__ __forceinline__ void ldsm4(uint32_t* r, uint32_t addr) {
    asm volatile("ldmatrix.sync.aligned.m8n8.x4.shared.b16 {%0,%1,%2,%3}, [%4];"
                 : "=r"(r[0]), "=r"(r[1]), "=r"(r[2]), "=r"(r[3]) : "r"(addr));
}
__device__ __forceinline__ void mma_f16(float* c, const uint32_t* a, uint32_t b0, uint32_t b1) {
    asm volatile("mma.sync.aligned.m16n8k16.row.col.f32.f16.f16.f32 "
                 "{%0,%1,%2,%3}, {%4,%5,%6,%7}, {%8,%9}, {%0,%1,%2,%3};"
                 : "+f"(c[0]), "+f"(c[1]), "+f"(c[2]), "+f"(c[3])
                 : "r"(a[0]), "r"(a[1]), "r"(a[2]), "r"(a[3]), "r"(b0), "r"(b1));
}

#define SROW 144

// ---------------------------------------------------------------------------
// Generic 1-term GEMM core: C[M,N] = A[M,K] @ W[N,K]^T (+bias)
// CTA tile 128 x (64*WN); warps 2(m) x WN(n); warp tile 64x64; BK=64;
// 2-stage cp.async.
// ---------------------------------------------------------------------------
template<int WN>
__device__ __forceinline__
void gemm_core(const __half* __restrict__ Ah, int lda,
               const __half* __restrict__ Wh, int ldw,
               const float* __restrict__ bias, float* __restrict__ C,
               int N, int K, char* smem)
{
    constexpr int NT      = 64 * WN;
    constexpr int THREADS = 64 * WN;
    constexpr int RP      = THREADS / 8;
    constexpr int A_BYTES = 128 * SROW;
    constexpr int SSZ     = (128 + NT) * SROW;

    const uint32_t sb = smem_u32(smem);
    const int tid  = threadIdx.x;
    const int lane = tid & 31;
    const int wid  = tid >> 5;
    const int warp_m = wid & 1;
    const int warp_n = wid >> 1;
    const int m0 = blockIdx.y * 128;
    const int n0 = blockIdx.x * NT;

    const __half* pAh = Ah + (size_t)m0 * lda;
    const __half* pWh = Wh + (size_t)n0 * ldw;

    float acc[4][8][4];
    #pragma unroll
    for (int a = 0; a < 4; a++)
        #pragma unroll
        for (int b = 0; b < 8; b++)
            #pragma unroll
            for (int c = 0; c < 4; c++) acc[a][b][c] = 0.0f;

    const uint32_t fr  = lane & 15;
    const uint32_t fcb = (lane >> 4) * 16;
    const int lr = tid >> 3;
    const int lc = tid & 7;
    const int nch = K / 64;

    auto load_stage = [&](uint32_t base, int k0) {
        #pragma unroll
        for (int i = 0; i < 128 / RP; i++) {
            int row = lr + i * RP;
            cpa16(base + row * SROW + lc * 16, pAh + (size_t)row * lda + k0 + lc * 8);
        }
        #pragma unroll
        for (int i = 0; i < NT / RP; i++) {
            int row = lr + i * RP;
            cpa16(base + A_BYTES + row * SROW + lc * 16, pWh + (size_t)row * ldw + k0 + lc * 8);
        }
    };

    load_stage(sb, 0);
    CP_COMMIT();

    for (int kc = 0; kc < nch; kc++) {
        if (kc + 1 < nch) {
            load_stage(sb + ((kc + 1) & 1) * SSZ, (kc + 1) * 64);
            CP_COMMIT();
            CP_WAIT(1);
        } else {
            CP_WAIT(0);
        }
        __syncthreads();

        const uint32_t stg = sb + (kc & 1) * SSZ;
        #pragma unroll
        for (int s = 0; s < 4; s++) {
            const uint32_t kb = s * 32 + fcb;
            uint32_t ah[4][4];
            #pragma unroll
            for (int mt = 0; mt < 4; mt++)
                ldsm4(ah[mt], stg + (warp_m * 64 + mt * 16 + fr) * SROW + kb);
            #pragma unroll
            for (int np = 0; np < 4; np++) {
                uint32_t w[4];
                ldsm4(w, stg + A_BYTES + (warp_n * 64 + np * 16 + fr) * SROW + kb);
                #pragma unroll
                for (int mt = 0; mt < 4; mt++) {
                    mma_f16(acc[mt][2*np],   ah[mt], w[0], w[2]);
                    mma_f16(acc[mt][2*np+1], ah[mt], w[1], w[3]);
                }
            }
        }
        __syncthreads();
    }

    const int er = lane >> 2;
    const int ec = (lane & 3) * 2;
    #pragma unroll
    for (int mt = 0; mt < 4; mt++) {
        const int row = m0 + warp_m * 64 + mt * 16 + er;
        #pragma unroll
        for (int nt = 0; nt < 8; nt++) {
            const int col = n0 + warp_n * 64 + nt * 8 + ec;
            float b0 = 0.f, b1 = 0.f;
            if (bias) { b0 = bias[col]; b1 = bias[col + 1]; }
            *(float2*)(C + (size_t)row * N + col) =
                make_float2(acc[mt][nt][0] + b0, acc[mt][nt][1] + b1);
            *(float2*)(C + (size_t)(row + 8) * N + col) =
                make_float2(acc[mt][nt][2] + b0, acc[mt][nt][3] + b1);
        }
    }
}

template<int WN>
__global__ __launch_bounds__(64*WN, 1)
void gemm_k(const __half* __restrict__ Ah, int lda,
            const __half* __restrict__ Wh, int ldw,
            const float* __restrict__ bias, float* __restrict__ C, int N, int K)
{
    extern __shared__ char smem[];
    gemm_core<WN>(Ah, lda, Wh, ldw, bias, C, N, K, smem);
}

// px / ph in one launch: blockIdx.z selects the set.
__global__ __launch_bounds__(256, 1)
void gemm_pxph(const __half* __restrict__ A0, const __half* __restrict__ W0,
               const float* __restrict__ b0, float* __restrict__ C0,
               const __half* __restrict__ A1, const __half* __restrict__ W1,
               float* __restrict__ C1, int lda)
{
    extern __shared__ char smem[];
    if (blockIdx.z == 0)
        gemm_core<4>(A0, lda, W0, UU, b0,      C0, FOURU, UU, smem);
    else
        gemm_core<4>(A1, lda, W1, UU, nullptr, C1, FOURU, UU, smem);
}

// ---------------------------------------------------------------------------
// gemm_s: fused d_x/d_h/d_b GEMM + gate combine.
//   s[row, j] = (aho@dxw + dx_b)*px + (aho@dhw + dh_b)*ph + (aho@dbw + db_b)
// CTA tile 128(m) x 128(j); warps 2(m) x 4(n); warp tile 64x32; K=256.
// A (128x256 fp16) fully resident in smem (4 chunks); W double-buffered,
// 12 chunk-loads (3 passes x 4 chunks).
// ---------------------------------------------------------------------------
#define S_ATILE (128 * SROW)
#define S_WOFF  (4 * S_ATILE)
#define S_SMEM  (S_WOFF + 2 * S_ATILE)   // 110592

__global__ __launch_bounds__(256, 1)
void gemm_s(const __half* __restrict__ A,          // aho [2048,256]
            const __half* __restrict__ Wall,       // [12288,256]
            const float* __restrict__ bx, const float* __restrict__ bh,
            const float* __restrict__ bb,
            const float* __restrict__ px, const float* __restrict__ ph,
            float* __restrict__ S)
{
    extern __shared__ char smem[];
    const uint32_t sb = smem_u32(smem);
    const int tid  = threadIdx.x;
    const int lane = tid & 31;
    const int wid  = tid >> 5;
    const int warp_m = wid & 1;     // 2 in m
    const int warp_n = wid >> 1;    // 4 in n
    const int m0 = blockIdx.y * 128;
    const int n0 = blockIdx.x * 128;

    const __half* pA = A + (size_t)m0 * HHU;

    const uint32_t fr  = lane & 15;
    const uint32_t fcb = (lane >> 4) * 16;
    const int lr = tid >> 3;    // 0..31
    const int lc = tid & 7;     // 0..7 (16B units; row = 64 halfs = 8 units)

    // load full A (4 chunks of 128x64) + first W chunk
    #pragma unroll
    for (int c = 0; c < 4; c++)
        #pragma unroll
        for (int i = 0; i < 4; i++) {
            int row = lr + i * 32;
            cpa16(sb + c * S_ATILE + row * SROW + lc * 16,
                  pA + (size_t)row * HHU + c * 64 + lc * 8);
        }
    // W chunk loader: pass t, chunk kc -> buffer
    auto load_w = [&](int t, int kc, int buf) {
        const __half* pW = Wall + (size_t)t * FOURU * HHU + (size_t)n0 * HHU;
        #pragma unroll
        for (int i = 0; i < 4; i++) {
            int row = lr + i * 32;
            cpa16(sb + S_WOFF + buf * S_ATILE + row * SROW + lc * 16,
                  pW + (size_t)row * HHU + kc * 64 + lc * 8);
        }
    };
    load_w(0, 0, 0);
    CP_COMMIT();

    float s_acc[4][4][4];
    #pragma unroll
    for (int a = 0; a < 4; a++)
        #pragma unroll
        for (int b = 0; b < 4; b++)
            #pragma unroll
            for (int c = 0; c < 4; c++) s_acc[a][b][c] = 0.0f;

    float acc[4][4][4];
    #pragma unroll
    for (int a = 0; a < 4; a++)
        #pragma unroll
        for (int b = 0; b < 4; b++)
            #pragma unroll
            for (int c = 0; c < 4; c++) acc[a][b][c] = 0.0f;

    const int er = lane >> 2;
    const int ec = (lane & 3) * 2;

    for (int i = 0; i < 12; i++) {
        const int kc = i & 3;
        if (i + 1 < 12) {
            load_w((i + 1) >> 2, (i + 1) & 3, (i + 1) & 1);
            CP_COMMIT();
            CP_WAIT(1);
        } else {
            CP_WAIT(0);
        }
        __syncthreads();

        const uint32_t wb = sb + S_WOFF + (i & 1) * S_ATILE;
        const uint32_t ab = sb + kc * S_ATILE;
        #pragma unroll
        for (int s = 0; s < 4; s++) {
            const uint32_t kb = s * 32 + fcb;
            uint32_t ah[4][4];
            #pragma unroll
            for (int mt = 0; mt < 4; mt++)
                ldsm4(ah[mt], ab + (warp_m * 64 + mt * 16 + fr) * SROW + kb);
            #pragma unroll
            for (int np = 0; np < 2; np++) {
                uint32_t w[4];
                ldsm4(w, wb + (warp_n * 32 + np * 16 + fr) * SROW + kb);
                #pragma unroll
                for (int mt = 0; mt < 4; mt++) {
                    mma_f16(acc[mt][2*np],   ah[mt], w[0], w[2]);
                    mma_f16(acc[mt][2*np+1], ah[mt], w[1], w[3]);
                }
            }
        }

        if (kc == 3) {
            // end of pass t: combine
            const int t = i >> 2;
            #pragma unroll
            for (int mt = 0; mt < 4; mt++) {
                const int row = m0 + warp_m * 64 + mt * 16 + er;
                #pragma unroll
                for (int nt = 0; nt < 4; nt++) {
                    const int col = n0 + warp_n * 32 + nt * 8 + ec;
                    if (t == 0) {
                        float2 p0 = *(const float2*)(px + (size_t)row * FOURU + col);
                        float2 p1 = *(const float2*)(px + (size_t)(row + 8) * FOURU + col);
                        float b0 = bx[col], b1 = bx[col + 1];
                        s_acc[mt][nt][0] += (acc[mt][nt][0] + b0) * p0.x;
                        s_acc[mt][nt][1] += (acc[mt][nt][1] + b1) * p0.y;
                        s_acc[mt][nt][2] += (acc[mt][nt][2] + b0) * p1.x;
                        s_acc[mt][nt][3] += (acc[mt][nt][3] + b1) * p1.y;
                    } else if (t == 1) {
                        float2 p0 = *(const float2*)(ph + (size_t)row * FOURU + col);
                        float2 p1 = *(const float2*)(ph + (size_t)(row + 8) * FOURU + col);
                        float b0 = bh[col], b1 = bh[col + 1];
                        s_acc[mt][nt][0] += (acc[mt][nt][0] + b0) * p0.x;
                        s_acc[mt][nt][1] += (acc[mt][nt][1] + b1) * p0.y;
                        s_acc[mt][nt][2] += (acc[mt][nt][2] + b0) * p1.x;
                        s_acc[mt][nt][3] += (acc[mt][nt][3] + b1) * p1.y;
                    } else {
                        float b0 = bb[col], b1 = bb[col + 1];
                        s_acc[mt][nt][0] += acc[mt][nt][0] + b0;
                        s_acc[mt][nt][1] += acc[mt][nt][1] + b1;
                        s_acc[mt][nt][2] += acc[mt][nt][2] + b0;
                        s_acc[mt][nt][3] += acc[mt][nt][3] + b1;
                    }
                    #pragma unroll
                    for (int c = 0; c < 4; c++) acc[mt][nt][c] = 0.0f;
                }
            }
        }
        __syncthreads();
    }

    // write s
    #pragma unroll
    for (int mt = 0; mt < 4; mt++) {
        const int row = m0 + warp_m * 64 + mt * 16 + er;
        #pragma unroll
        for (int nt = 0; nt < 4; nt++) {
            const int col = n0 + warp_n * 32 + nt * 8 + ec;
            *(float2*)(S + (size_t)row * FOURU + col) =
                make_float2(s_acc[mt][nt][0], s_acc[mt][nt][1]);
            *(float2*)(S + (size_t)(row + 8) * FOURU + col) =
                make_float2(s_acc[mt][nt][2], s_acc[mt][nt][3]);
        }
    }
}

// ---------------------------------------------------------------------------
// prep: concat + fp16 activations -> [2048, 2304]
// ---------------------------------------------------------------------------
__global__ void concat_fp16(const float* __restrict__ inputs,
                            const float* __restrict__ main_h,
                            const float* __restrict__ hyper_h,
                            __half* __restrict__ Dh)
{
    int i4 = blockIdx.x * blockDim.x + threadIdx.x;
    if (i4 >= BB * KHYP / 4) return;
    int row = i4 / (KHYP / 4);
    int c4  = (i4 - row * (KHYP / 4)) * 4;
    const float* src;
    if (c4 < DD)            src = inputs  + (size_t)row * DD  + c4;
    else if (c4 < DD + UU)  src = main_h  + (size_t)row * UU  + (c4 - DD);
    else                    src = hyper_h + (size_t)row * HHU + (c4 - DD - UU);
    float4 v = *(const float4*)src;
    size_t o = (size_t)row * KHYP + c4;
    unsigned short hs[4];
    hs[0] = __half_as_ushort(__float2half_rn(v.x));
    hs[1] = __half_as_ushort(__float2half_rn(v.y));
    hs[2] = __half_as_ushort(__float2half_rn(v.z));
    hs[3] = __half_as_ushort(__float2half_rn(v.w));
    *(uint2*)(Dh + o) = make_uint2((uint32_t)hs[0] | ((uint32_t)hs[1] << 16),
                                   (uint32_t)hs[2] | ((uint32_t)hs[3] << 16));
}

// ---------------------------------------------------------------------------
// prep: transpose weight tiles
// ---------------------------------------------------------------------------
__device__ __forceinline__ void trans_tile(const float* __restrict__ W,
                                           __half* __restrict__ Th,
                                           int N, int dstLd, int kOff,
                                           int n0, int k0)
{
    __shared__ float t[64][33];
    const int tx = threadIdx.x, ty = threadIdx.y;   // 32 x 8
    #pragma unroll
    for (int i = 0; i < 8; i++)
        t[ty + i * 8][tx] = W[(size_t)(k0 + ty + i * 8) * N + n0 + tx];
    __syncthreads();
    #pragma unroll
    for (int j = 0; j < 4; j++) {
        int n = ty + j * 8;
        float v0 = t[tx * 2][n], v1 = t[tx * 2 + 1][n];
        uint32_t pk = (uint32_t)__half_as_ushort(__float2half_rn(v0))
                    | ((uint32_t)__half_as_ushort(__float2half_rn(v1)) << 16);
        *(uint32_t*)(Th + (size_t)(n0 + n) * dstLd + kOff + k0 + tx * 2) = pk;
    }
}

__global__ void trans_d3(const float* __restrict__ w0, const float* __restrict__ w1,
                         const float* __restrict__ w2, __half* __restrict__ Tall)
{
    const float* W = (blockIdx.z == 0) ? w0 : (blockIdx.z == 1) ? w1 : w2;
    trans_tile(W, Tall + (size_t)blockIdx.z * FOURU * HHU, FOURU, HHU, 0,
               blockIdx.x * 32, blockIdx.y * 64);
}

__global__ void trans_kr(const float* __restrict__ kw, const float* __restrict__ rw,
                         __half* __restrict__ Tk, __half* __restrict__ Tr)
{
    const float* W = blockIdx.z ? rw : kw;
    __half* T = blockIdx.z ? Tr : Tk;
    trans_tile(W, T, FOURU, UU, 0, blockIdx.x * 32, blockIdx.y * 64);
}

__global__ void trans_hyp(const float* __restrict__ hk, const float* __restrict__ hr,
                          __half* __restrict__ T)
{
    if (blockIdx.z == 0) {
        trans_tile(hk, T, FOURHU, KHYP, 0, blockIdx.x * 32, blockIdx.y * 64);
    } else {
        if (blockIdx.y >= HHU / 64) return;
        trans_tile(hr, T, FOURHU, KHYP, DD + UU, blockIdx.x * 32, blockIdx.y * 64);
    }
}

// ---------------------------------------------------------------------------
// hyper LSTM pointwise (+ fp16 of hyper_out)
// ---------------------------------------------------------------------------
__global__ void hyper_pointwise(const float* __restrict__ z,
                                const float* __restrict__ hyper_c,
                                float* __restrict__ hyper_out,
                                float* __restrict__ hyper_c_new,
                                __half* __restrict__ hoh)
{
    int idx = blockIdx.x * blockDim.x + threadIdx.x;
    if (idx >= BB * HHU) return;
    int b = idx / HHU;
    int u = idx - b * HHU;
    const float* zr = z + (size_t)b * FOURHU;
    float hi = zr[u];
    float hf = zr[HHU + u];
    float hg = zr[2 * HHU + u];
    float ho = zr[3 * HHU + u];
    float c = sigf(hf) * hyper_c[idx] + sigf(hi) * tanhf(hg);
    hyper_c_new[idx] = c;
    float out = sigf(ho) * tanhf(c);
    hyper_out[idx] = out;
    hoh[idx] = __float2half_rn(out);
}

// ---------------------------------------------------------------------------
// LN epilogue: gates = LN(s); c,h update
// ---------------------------------------------------------------------------
__device__ __forceinline__ void block_reduce2(float& a, float& b, float* sm)
{
    __syncthreads();
    #pragma unroll
    for (int o = 16; o > 0; o >>= 1) {
        a += __shfl_down_sync(0xffffffffu, a, o);
        b += __shfl_down_sync(0xffffffffu, b, o);
    }
    int w = threadIdx.x >> 5, l = threadIdx.x & 31;
    if (l == 0) { sm[w] = a; sm[32 + w] = b; }
    __syncthreads();
    if (w == 0) {
        int nw = blockDim.x >> 5;
        a = (l < nw) ? sm[l] : 0.0f;
        b = (l < nw) ? sm[32 + l] : 0.0f;
        #pragma unroll
        for (int o = 16; o > 0; o >>= 1) {
            a += __shfl_down_sync(0xffffffffu, a, o);
            b += __shfl_down_sync(0xffffffffu, b, o);
        }
        if (l == 0) { sm[0] = a; sm[32] = b; }
    }
    __syncthreads();
    a = sm[0];
    b = sm[32];
}

__global__ __launch_bounds__(512)
void main_epilogue(const float* __restrict__ S, const float* __restrict__ main_c,
                   float* __restrict__ out_h, float* __restrict__ out_c)
{
    __shared__ float sm[64];
    const int b = blockIdx.x;
    const int t = threadIdx.x;
    const size_t b4 = (size_t)b * FOURU;

    float s[8];
    float sum = 0.0f, sq = 0.0f;
    #pragma unroll
    for (int r = 0; r < 8; r++) {
        float v = S[b4 + t + r * 512];
        s[r] = v;
        sum += v;
        sq = fmaf(v, v, sq);
    }
    block_reduce2(sum, sq, sm);
    float mean = sum * (1.0f / 4096.0f);
    float var = sq * (1.0f / 4096.0f) - mean * mean;
    float inv = rsqrtf(var + 1e-3f);

    float i0 = (s[0] - mean) * inv, i1 = (s[1] - mean) * inv;
    float f0 = (s[2] - mean) * inv, f1 = (s[3] - mean) * inv;
    float g0 = (s[4] - mean) * inv, g1 = (s[5] - mean) * inv;
    float o0 = (s[6] - mean) * inv, o1 = (s[7] - mean) * inv;

    const size_t cb = (size_t)b * UU;
    float c0 = sigf(f0) * main_c[cb + t]       + sigf(i0) * tanhf(g0);
    float c1 = sigf(f1) * main_c[cb + t + 512] + sigf(i1) * tanhf(g1);

    float sum2 = c0 + c1;
    float sq2 = fmaf(c0, c0, c1 * c1);
    block_reduce2(sum2, sq2, sm);
    float mean2 = sum2 * (1.0f / 1024.0f);
    float var2 = sq2 * (1.0f / 1024.0f) - mean2 * mean2;
    float inv2 = rsqrtf(var2 + 1e-3f);

    float h0 = sigf(o0) * tanhf((c0 - mean2) * inv2);
    float h1 = sigf(o1) * tanhf((c1 - mean2) * inv2);

    out_c[cb + t] = c0;
    out_c[cb + t + 512] = c1;
    out_h[cb + t] = h0;
    out_h[cb + t + 512] = h1;
}

// ---------------------------------------------------------------------------
// launch
// ---------------------------------------------------------------------------
extern "C" void kernel_launch(void* const* d_in, const int* in_sizes, int n_in,
                              void* d_out, int out_size)
{
    const float* inputs       = (const float*)d_in[0];
    const float* main_h       = (const float*)d_in[1];
    const float* main_c       = (const float*)d_in[2];
    const float* hyper_h      = (const float*)d_in[3];
    const float* hyper_c      = (const float*)d_in[4];
    const float* kernel_w     = (const float*)d_in[5];
    const float* rec_w        = (const float*)d_in[6];
    const float* bias         = (const float*)d_in[7];
    const float* hyper_kernel = (const float*)d_in[8];
    const float* hyper_rec    = (const float*)d_in[9];
    const float* hyper_bias   = (const float*)d_in[10];
    const float* dx_w         = (const float*)d_in[11];
    const float* dx_b         = (const float*)d_in[12];
    const float* dh_w         = (const float*)d_in[13];
    const float* dh_b         = (const float*)d_in[14];
    const float* db_w         = (const float*)d_in[15];
    const float* db_b         = (const float*)d_in[16];

    float* out = (float*)d_out;
    float* out_h  = out;
    float* out_c  = out + (size_t)BB * UU;
    float* out_ho = out + (size_t)2 * BB * UU;
    float* out_hc = out_ho + (size_t)BB * HHU;

    float *z, *s, *px, *phv;
    cudaGetSymbolAddress((void**)&z,   g_z);
    cudaGetSymbolAddress((void**)&s,   g_s);
    cudaGetSymbolAddress((void**)&px,  g_px);
    cudaGetSymbolAddress((void**)&phv, g_ph);

    __half *ahyp, *aho, *wthyp, *wtall, *wtk, *wtr;
    cudaGetSymbolAddress((void**)&ahyp,  g_ahyp);
    cudaGetSymbolAddress((void**)&aho,   g_aho);
    cudaGetSymbolAddress((void**)&wthyp, g_wthyp);
    cudaGetSymbolAddress((void**)&wtall, g_wtall);
    cudaGetSymbolAddress((void**)&wtk,   g_wtk);
    cudaGetSymbolAddress((void**)&wtr,   g_wtr);

    constexpr int SSZ_H = (128 + 128) * SROW;   // WN=2
    constexpr int SSZ_4 = (128 + 256) * SROW;   // WN=4
    cudaFuncSetAttribute(gemm_k<2>,  cudaFuncAttributeMaxDynamicSharedMemorySize, 2 * SSZ_H);
    cudaFuncSetAttribute(gemm_pxph, cudaFuncAttributeMaxDynamicSharedMemorySize, 2 * SSZ_4);
    cudaFuncSetAttribute(gemm_s,    cudaFuncAttributeMaxDynamicSharedMemorySize, S_SMEM);

    dim3 tb(32, 8);

    // ---- prep ----
    concat_fp16<<<(BB * KHYP / 4 + 255) / 256, 256>>>(inputs, main_h, hyper_h, ahyp);
    trans_hyp<<<dim3(FOURHU/32, (DD+UU)/64, 2), tb>>>(hyper_kernel, hyper_rec, wthyp);
    trans_d3 <<<dim3(FOURU/32, HHU/64, 3), tb>>>(dx_w, dh_w, db_w, wtall);
    trans_kr <<<dim3(FOURU/32, UU/64, 2), tb>>>(kernel_w, rec_w, wtk, wtr);

    // ---- px & ph (independent of hyper chain) ----
    gemm_pxph<<<dim3(FOURU/256, BB/128, 2), 256, 2*SSZ_4>>>(
        ahyp, wtk, bias, px, ahyp + DD, wtr, phv, KHYP);

    // ---- hyper GEMM (1-term): z = ahyp @ wthyp^T + hyper_bias ----
    gemm_k<2><<<dim3(FOURHU/128, BB/128), 128, 2*SSZ_H>>>(
        ahyp, KHYP, wthyp, KHYP, hyper_bias, z, FOURHU, KHYP);

    // ---- hyper pointwise ----
    hyper_pointwise<<<(BB * HHU + 255) / 256, 256>>>(z, hyper_c, out_ho, out_hc, aho);

    // ---- fused d-GEMM + gate combine -> s ----
    gemm_s<<<dim3(FOURU/128, BB/128), 256, S_SMEM>>>(
        aho, wtall, dx_b, dh_b, db_b, px, phv, s);

    // ---- LN + LSTM epilogue ----
    main_epilogue<<<BB, 512>>>(s, main_c, out_h, out_c);
}

// round 7
// speedup vs baseline: 5.9997x; 1.0202x over previous
#include <cuda_runtime.h>
#include <cuda_fp16.h>
#include <math.h>
#include <cstdint>

#define BB 2048
#define DD 1024
#define UU 1024
#define HHU 256
#define FOURU (4*UU)     // 4096
#define FOURHU (4*HHU)   // 1024
#define KHYP (DD+UU+HHU) // 2304
#define N3 (3*FOURU)     // 12288

// ---------------------------------------------------------------------------
// scratch (static device arrays; no allocation allowed)
// ---------------------------------------------------------------------------
__device__ float g_z [BB * FOURHU];
__device__ float g_s [BB * FOURU];    // fused gate pre-activations
__device__ float g_px[BB * FOURU];
__device__ float g_ph[BB * FOURU];

// fp16 activations
__device__ __half g_ahyp[BB * KHYP];   // fp16 of [inputs|main_h|hyper_h]
__device__ __half g_aho [BB * HHU];    // fp16 of hyper_out
// transposed fp16 weights ([N, K] row-major, k-contiguous)
__device__ __half g_wthyp[FOURHU * KHYP];
__device__ __half g_wtall[N3 * HHU];   // dx_w^T | dh_w^T | db_w^T stacked on N
__device__ __half g_wtk[FOURU * UU];
__device__ __half g_wtr[FOURU * UU];

__device__ __forceinline__ float sigf(float x) { return 1.0f / (1.0f + expf(-x)); }

__device__ __forceinline__ uint32_t smem_u32(const void* p) {
    uint32_t a;
    asm("{ .reg .u64 t; cvta.to.shared.u64 t, %1; cvt.u32.u64 %0, t; }" : "=r"(a) : "l"(p));
    return a;
}
__device__ __forceinline__ void cpa16(uint32_t dst, const void* src) {
    asm volatile("cp.async.cg.shared.global [%0], [%1], 16;" :: "r"(dst), "l"(src));
}
#define CP_COMMIT() asm volatile("cp.async.commit_group;" ::: "memory")
#define CP_WAIT(n)  asm volatile("cp.async.wait_group %0;" :: "n"(n) : "memory")

__device__ __forceinline__ void ldsm4(uint32_t* r, uint32_t addr) {
    asm volatile("ldmatrix.sync.aligned.m8n8.x4.shared.b16 {%0,%1,%2,%3}, [%4];"
                 : "=r"(r[0]), "=r"(r[1]), "=r"(r[2]), "=r"(r[3]) : "r"(addr));
}
__device__ __forceinline__ void mma_f16(float* c, const uint32_t* a, uint32_t b0, uint32_t b1) {
    asm volatile("mma.sync.aligned.m16n8k16.row.col.f32.f16.f16.f32 "
                 "{%0,%1,%2,%3}, {%4,%5,%6,%7}, {%8,%9}, {%0,%1,%2,%3};"
                 : "+f"(c[0]), "+f"(c[1]), "+f"(c[2]), "+f"(c[3])
                 : "r"(a[0]), "r"(a[1]), "r"(a[2]), "r"(a[3]), "r"(b0), "r"(b1));
}

#define SROW 144

// ---------------------------------------------------------------------------
// Generic 1-term GEMM core: C[M,N] = A[M,K] @ W[N,K]^T (+bias)
// CTA tile 128 x (64*WN); warps 2(m) x WN(n); warp tile 64x64; BK=64;
// 2-stage cp.async.
// ---------------------------------------------------------------------------
template<int WN>
__device__ __forceinline__
void gemm_core(const __half* __restrict__ Ah, int lda,
               const __half* __restrict__ Wh, int ldw,
               const float* __restrict__ bias, float* __restrict__ C,
               int N, int K, char* smem)
{
    constexpr int NT      = 64 * WN;
    constexpr int THREADS = 64 * WN;
    constexpr int RP      = THREADS / 8;
    constexpr int A_BYTES = 128 * SROW;
    constexpr int SSZ     = (128 + NT) * SROW;

    const uint32_t sb = smem_u32(smem);
    const int tid  = threadIdx.x;
    const int lane = tid & 31;
    const int wid  = tid >> 5;
    const int warp_m = wid & 1;
    const int warp_n = wid >> 1;
    const int m0 = blockIdx.y * 128;
    const int n0 = blockIdx.x * NT;

    const __half* pAh = Ah + (size_t)m0 * lda;
    const __half* pWh = Wh + (size_t)n0 * ldw;

    float acc[4][8][4];
    #pragma unroll
    for (int a = 0; a < 4; a++)
        #pragma unroll
        for (int b = 0; b < 8; b++)
            #pragma unroll
            for (int c = 0; c < 4; c++) acc[a][b][c] = 0.0f;

    const uint32_t fr  = lane & 15;
    const uint32_t fcb = (lane >> 4) * 16;
    const int lr = tid >> 3;
    const int lc = tid & 7;
    const int nch = K / 64;

    auto load_stage = [&](uint32_t base, int k0) {
        #pragma unroll
        for (int i = 0; i < 128 / RP; i++) {
            int row = lr + i * RP;
            cpa16(base + row * SROW + lc * 16, pAh + (size_t)row * lda + k0 + lc * 8);
        }
        #pragma unroll
        for (int i = 0; i < NT / RP; i++) {
            int row = lr + i * RP;
            cpa16(base + A_BYTES + row * SROW + lc * 16, pWh + (size_t)row * ldw + k0 + lc * 8);
        }
    };

    load_stage(sb, 0);
    CP_COMMIT();

    for (int kc = 0; kc < nch; kc++) {
        if (kc + 1 < nch) {
            load_stage(sb + ((kc + 1) & 1) * SSZ, (kc + 1) * 64);
            CP_COMMIT();
            CP_WAIT(1);
        } else {
            CP_WAIT(0);
        }
        __syncthreads();

        const uint32_t stg = sb + (kc & 1) * SSZ;
        #pragma unroll
        for (int s = 0; s < 4; s++) {
            const uint32_t kb = s * 32 + fcb;
            uint32_t ah[4][4];
            #pragma unroll
            for (int mt = 0; mt < 4; mt++)
                ldsm4(ah[mt], stg + (warp_m * 64 + mt * 16 + fr) * SROW + kb);
            #pragma unroll
            for (int np = 0; np < 4; np++) {
                uint32_t w[4];
                ldsm4(w, stg + A_BYTES + (warp_n * 64 + np * 16 + fr) * SROW + kb);
                #pragma unroll
                for (int mt = 0; mt < 4; mt++) {
                    mma_f16(acc[mt][2*np],   ah[mt], w[0], w[2]);
                    mma_f16(acc[mt][2*np+1], ah[mt], w[1], w[3]);
                }
            }
        }
        __syncthreads();
    }

    const int er = lane >> 2;
    const int ec = (lane & 3) * 2;
    #pragma unroll
    for (int mt = 0; mt < 4; mt++) {
        const int row = m0 + warp_m * 64 + mt * 16 + er;
        #pragma unroll
        for (int nt = 0; nt < 8; nt++) {
            const int col = n0 + warp_n * 64 + nt * 8 + ec;
            float b0 = 0.f, b1 = 0.f;
            if (bias) { b0 = bias[col]; b1 = bias[col + 1]; }
            *(float2*)(C + (size_t)row * N + col) =
                make_float2(acc[mt][nt][0] + b0, acc[mt][nt][1] + b1);
            *(float2*)(C + (size_t)(row + 8) * N + col) =
                make_float2(acc[mt][nt][2] + b0, acc[mt][nt][3] + b1);
        }
    }
}

template<int WN>
__global__ __launch_bounds__(64*WN, 1)
void gemm_k(const __half* __restrict__ Ah, int lda,
            const __half* __restrict__ Wh, int ldw,
            const float* __restrict__ bias, float* __restrict__ C, int N, int K)
{
    extern __shared__ char smem[];
    gemm_core<WN>(Ah, lda, Wh, ldw, bias, C, N, K, smem);
}

// px / ph in one launch: blockIdx.z selects the set.
__global__ __launch_bounds__(256, 1)
void gemm_pxph(const __half* __restrict__ A0, const __half* __restrict__ W0,
               const float* __restrict__ b0, float* __restrict__ C0,
               const __half* __restrict__ A1, const __half* __restrict__ W1,
               float* __restrict__ C1, int lda)
{
    extern __shared__ char smem[];
    if (blockIdx.z == 0)
        gemm_core<4>(A0, lda, W0, UU, b0,      C0, FOURU, UU, smem);
    else
        gemm_core<4>(A1, lda, W1, UU, nullptr, C1, FOURU, UU, smem);
}

// ---------------------------------------------------------------------------
// gemm_s: fused d_x/d_h/d_b GEMM + gate combine.
//   s[row, j] = (aho@dxw + dx_b)*px + (aho@dhw + dh_b)*ph + (aho@dbw + db_b)
// CTA tile 128(m) x 128(j); warps 2(m) x 4(n); warp tile 64x32; K=256.
// A fully resident in smem; W double-buffered; 3 passes x 4 chunks.
// ---------------------------------------------------------------------------
#define S_ATILE (128 * SROW)
#define S_WOFF  (4 * S_ATILE)
#define S_SMEM  (S_WOFF + 2 * S_ATILE)   // 110592

__global__ __launch_bounds__(256, 1)
void gemm_s(const __half* __restrict__ A,          // aho [2048,256]
            const __half* __restrict__ Wall,       // [12288,256]
            const float* __restrict__ bx, const float* __restrict__ bh,
            const float* __restrict__ bb,
            const float* __restrict__ px, const float* __restrict__ ph,
            float* __restrict__ S)
{
    extern __shared__ char smem[];
    const uint32_t sb = smem_u32(smem);
    const int tid  = threadIdx.x;
    const int lane = tid & 31;
    const int wid  = tid >> 5;
    const int warp_m = wid & 1;
    const int warp_n = wid >> 1;
    const int m0 = blockIdx.y * 128;
    const int n0 = blockIdx.x * 128;

    const __half* pA = A + (size_t)m0 * HHU;

    const uint32_t fr  = lane & 15;
    const uint32_t fcb = (lane >> 4) * 16;
    const int lr = tid >> 3;
    const int lc = tid & 7;

    #pragma unroll
    for (int c = 0; c < 4; c++)
        #pragma unroll
        for (int i = 0; i < 4; i++) {
            int row = lr + i * 32;
            cpa16(sb + c * S_ATILE + row * SROW + lc * 16,
                  pA + (size_t)row * HHU + c * 64 + lc * 8);
        }
    auto load_w = [&](int t, int kc, int buf) {
        const __half* pW = Wall + (size_t)t * FOURU * HHU + (size_t)n0 * HHU;
        #pragma unroll
        for (int i = 0; i < 4; i++) {
            int row = lr + i * 32;
            cpa16(sb + S_WOFF + buf * S_ATILE + row * SROW + lc * 16,
                  pW + (size_t)row * HHU + kc * 64 + lc * 8);
        }
    };
    load_w(0, 0, 0);
    CP_COMMIT();

    float s_acc[4][4][4];
    #pragma unroll
    for (int a = 0; a < 4; a++)
        #pragma unroll
        for (int b = 0; b < 4; b++)
            #pragma unroll
            for (int c = 0; c < 4; c++) s_acc[a][b][c] = 0.0f;

    float acc[4][4][4];
    #pragma unroll
    for (int a = 0; a < 4; a++)
        #pragma unroll
        for (int b = 0; b < 4; b++)
            #pragma unroll
            for (int c = 0; c < 4; c++) acc[a][b][c] = 0.0f;

    const int er = lane >> 2;
    const int ec = (lane & 3) * 2;

    for (int i = 0; i < 12; i++) {
        const int kc = i & 3;
        if (i + 1 < 12) {
            load_w((i + 1) >> 2, (i + 1) & 3, (i + 1) & 1);
            CP_COMMIT();
            CP_WAIT(1);
        } else {
            CP_WAIT(0);
        }
        __syncthreads();

        const uint32_t wb = sb + S_WOFF + (i & 1) * S_ATILE;
        const uint32_t ab = sb + kc * S_ATILE;
        #pragma unroll
        for (int s = 0; s < 4; s++) {
            const uint32_t kb = s * 32 + fcb;
            uint32_t ah[4][4];
            #pragma unroll
            for (int mt = 0; mt < 4; mt++)
                ldsm4(ah[mt], ab + (warp_m * 64 + mt * 16 + fr) * SROW + kb);
            #pragma unroll
            for (int np = 0; np < 2; np++) {
                uint32_t w[4];
                ldsm4(w, wb + (warp_n * 32 + np * 16 + fr) * SROW + kb);
                #pragma unroll
                for (int mt = 0; mt < 4; mt++) {
                    mma_f16(acc[mt][2*np],   ah[mt], w[0], w[2]);
                    mma_f16(acc[mt][2*np+1], ah[mt], w[1], w[3]);
                }
            }
        }

        if (kc == 3) {
            const int t = i >> 2;
            #pragma unroll
            for (int mt = 0; mt < 4; mt++) {
                const int row = m0 + warp_m * 64 + mt * 16 + er;
                #pragma unroll
                for (int nt = 0; nt < 4; nt++) {
                    const int col = n0 + warp_n * 32 + nt * 8 + ec;
                    if (t == 0) {
                        float2 p0 = *(const float2*)(px + (size_t)row * FOURU + col);
                        float2 p1 = *(const float2*)(px + (size_t)(row + 8) * FOURU + col);
                        float b0 = bx[col], b1 = bx[col + 1];
                        s_acc[mt][nt][0] += (acc[mt][nt][0] + b0) * p0.x;
                        s_acc[mt][nt][1] += (acc[mt][nt][1] + b1) * p0.y;
                        s_acc[mt][nt][2] += (acc[mt][nt][2] + b0) * p1.x;
                        s_acc[mt][nt][3] += (acc[mt][nt][3] + b1) * p1.y;
                    } else if (t == 1) {
                        float2 p0 = *(const float2*)(ph + (size_t)row * FOURU + col);
                        float2 p1 = *(const float2*)(ph + (size_t)(row + 8) * FOURU + col);
                        float b0 = bh[col], b1 = bh[col + 1];
                        s_acc[mt][nt][0] += (acc[mt][nt][0] + b0) * p0.x;
                        s_acc[mt][nt][1] += (acc[mt][nt][1] + b1) * p0.y;
                        s_acc[mt][nt][2] += (acc[mt][nt][2] + b0) * p1.x;
                        s_acc[mt][nt][3] += (acc[mt][nt][3] + b1) * p1.y;
                    } else {
                        float b0 = bb[col], b1 = bb[col + 1];
                        s_acc[mt][nt][0] += acc[mt][nt][0] + b0;
                        s_acc[mt][nt][1] += acc[mt][nt][1] + b1;
                        s_acc[mt][nt][2] += acc[mt][nt][2] + b0;
                        s_acc[mt][nt][3] += acc[mt][nt][3] + b1;
                    }
                    #pragma unroll
                    for (int c = 0; c < 4; c++) acc[mt][nt][c] = 0.0f;
                }
            }
        }
        __syncthreads();
    }

    #pragma unroll
    for (int mt = 0; mt < 4; mt++) {
        const int row = m0 + warp_m * 64 + mt * 16 + er;
        #pragma unroll
        for (int nt = 0; nt < 4; nt++) {
            const int col = n0 + warp_n * 32 + nt * 8 + ec;
            *(float2*)(S + (size_t)row * FOURU + col) =
                make_float2(s_acc[mt][nt][0], s_acc[mt][nt][1]);
            *(float2*)(S + (size_t)(row + 8) * FOURU + col) =
                make_float2(s_acc[mt][nt][2], s_acc[mt][nt][3]);
        }
    }
}

// ---------------------------------------------------------------------------
// prep kernels
// ---------------------------------------------------------------------------
__global__ void concat_fp16(const float* __restrict__ inputs,
                            const float* __restrict__ main_h,
                            const float* __restrict__ hyper_h,
                            __half* __restrict__ Dh)
{
    int i4 = blockIdx.x * blockDim.x + threadIdx.x;
    if (i4 >= BB * KHYP / 4) return;
    int row = i4 / (KHYP / 4);
    int c4  = (i4 - row * (KHYP / 4)) * 4;
    const float* src;
    if (c4 < DD)            src = inputs  + (size_t)row * DD  + c4;
    else if (c4 < DD + UU)  src = main_h  + (size_t)row * UU  + (c4 - DD);
    else                    src = hyper_h + (size_t)row * HHU + (c4 - DD - UU);
    float4 v = *(const float4*)src;
    size_t o = (size_t)row * KHYP + c4;
    unsigned short hs[4];
    hs[0] = __half_as_ushort(__float2half_rn(v.x));
    hs[1] = __half_as_ushort(__float2half_rn(v.y));
    hs[2] = __half_as_ushort(__float2half_rn(v.z));
    hs[3] = __half_as_ushort(__float2half_rn(v.w));
    *(uint2*)(Dh + o) = make_uint2((uint32_t)hs[0] | ((uint32_t)hs[1] << 16),
                                   (uint32_t)hs[2] | ((uint32_t)hs[3] << 16));
}

__device__ __forceinline__ void trans_tile(const float* __restrict__ W,
                                           __half* __restrict__ Th,
                                           int N, int dstLd, int kOff,
                                           int n0, int k0)
{
    __shared__ float t[64][33];
    const int tx = threadIdx.x, ty = threadIdx.y;   // 32 x 8
    #pragma unroll
    for (int i = 0; i < 8; i++)
        t[ty + i * 8][tx] = W[(size_t)(k0 + ty + i * 8) * N + n0 + tx];
    __syncthreads();
    #pragma unroll
    for (int j = 0; j < 4; j++) {
        int n = ty + j * 8;
        float v0 = t[tx * 2][n], v1 = t[tx * 2 + 1][n];
        uint32_t pk = (uint32_t)__half_as_ushort(__float2half_rn(v0))
                    | ((uint32_t)__half_as_ushort(__float2half_rn(v1)) << 16);
        *(uint32_t*)(Th + (size_t)(n0 + n) * dstLd + kOff + k0 + tx * 2) = pk;
    }
}

__global__ void trans_d3(const float* __restrict__ w0, const float* __restrict__ w1,
                         const float* __restrict__ w2, __half* __restrict__ Tall)
{
    const float* W = (blockIdx.z == 0) ? w0 : (blockIdx.z == 1) ? w1 : w2;
    trans_tile(W, Tall + (size_t)blockIdx.z * FOURU * HHU, FOURU, HHU, 0,
               blockIdx.x * 32, blockIdx.y * 64);
}

__global__ void trans_kr(const float* __restrict__ kw, const float* __restrict__ rw,
                         __half* __restrict__ Tk, __half* __restrict__ Tr)
{
    const float* W = blockIdx.z ? rw : kw;
    __half* T = blockIdx.z ? Tr : Tk;
    trans_tile(W, T, FOURU, UU, 0, blockIdx.x * 32, blockIdx.y * 64);
}

__global__ void trans_hyp(const float* __restrict__ hk, const float* __restrict__ hr,
                          __half* __restrict__ T)
{
    if (blockIdx.z == 0) {
        trans_tile(hk, T, FOURHU, KHYP, 0, blockIdx.x * 32, blockIdx.y * 64);
    } else {
        if (blockIdx.y >= HHU / 64) return;
        trans_tile(hr, T, FOURHU, KHYP, DD + UU, blockIdx.x * 32, blockIdx.y * 64);
    }
}

// ---------------------------------------------------------------------------
// hyper LSTM pointwise (+ fp16 of hyper_out)
// ---------------------------------------------------------------------------
__global__ void hyper_pointwise(const float* __restrict__ z,
                                const float* __restrict__ hyper_c,
                                float* __restrict__ hyper_out,
                                float* __restrict__ hyper_c_new,
                                __half* __restrict__ hoh)
{
    int idx = blockIdx.x * blockDim.x + threadIdx.x;
    if (idx >= BB * HHU) return;
    int b = idx / HHU;
    int u = idx - b * HHU;
    const float* zr = z + (size_t)b * FOURHU;
    float hi = zr[u];
    float hf = zr[HHU + u];
    float hg = zr[2 * HHU + u];
    float ho = zr[3 * HHU + u];
    float c = sigf(hf) * hyper_c[idx] + sigf(hi) * tanhf(hg);
    hyper_c_new[idx] = c;
    float out = sigf(ho) * tanhf(c);
    hyper_out[idx] = out;
    hoh[idx] = __float2half_rn(out);
}

// ---------------------------------------------------------------------------
// LN epilogue
// ---------------------------------------------------------------------------
__device__ __forceinline__ void block_reduce2(float& a, float& b, float* sm)
{
    __syncthreads();
    #pragma unroll
    for (int o = 16; o > 0; o >>= 1) {
        a += __shfl_down_sync(0xffffffffu, a, o);
        b += __shfl_down_sync(0xffffffffu, b, o);
    }
    int w = threadIdx.x >> 5, l = threadIdx.x & 31;
    if (l == 0) { sm[w] = a; sm[32 + w] = b; }
    __syncthreads();
    if (w == 0) {
        int nw = blockDim.x >> 5;
        a = (l < nw) ? sm[l] : 0.0f;
        b = (l < nw) ? sm[32 + l] : 0.0f;
        #pragma unroll
        for (int o = 16; o > 0; o >>= 1) {
            a += __shfl_down_sync(0xffffffffu, a, o);
            b += __shfl_down_sync(0xffffffffu, b, o);
        }
        if (l == 0) { sm[0] = a; sm[32] = b; }
    }
    __syncthreads();
    a = sm[0];
    b = sm[32];
}

__global__ __launch_bounds__(512)
void main_epilogue(const float* __restrict__ S, const float* __restrict__ main_c,
                   float* __restrict__ out_h, float* __restrict__ out_c)
{
    __shared__ float sm[64];
    const int b = blockIdx.x;
    const int t = threadIdx.x;
    const size_t b4 = (size_t)b * FOURU;

    float s[8];
    float sum = 0.0f, sq = 0.0f;
    #pragma unroll
    for (int r = 0; r < 8; r++) {
        float v = S[b4 + t + r * 512];
        s[r] = v;
        sum += v;
        sq = fmaf(v, v, sq);
    }
    block_reduce2(sum, sq, sm);
    float mean = sum * (1.0f / 4096.0f);
    float var = sq * (1.0f / 4096.0f) - mean * mean;
    float inv = rsqrtf(var + 1e-3f);

    float i0 = (s[0] - mean) * inv, i1 = (s[1] - mean) * inv;
    float f0 = (s[2] - mean) * inv, f1 = (s[3] - mean) * inv;
    float g0 = (s[4] - mean) * inv, g1 = (s[5] - mean) * inv;
    float o0 = (s[6] - mean) * inv, o1 = (s[7] - mean) * inv;

    const size_t cb = (size_t)b * UU;
    float c0 = sigf(f0) * main_c[cb + t]       + sigf(i0) * tanhf(g0);
    float c1 = sigf(f1) * main_c[cb + t + 512] + sigf(i1) * tanhf(g1);

    float sum2 = c0 + c1;
    float sq2 = fmaf(c0, c0, c1 * c1);
    block_reduce2(sum2, sq2, sm);
    float mean2 = sum2 * (1.0f / 1024.0f);
    float var2 = sq2 * (1.0f / 1024.0f) - mean2 * mean2;
    float inv2 = rsqrtf(var2 + 1e-3f);

    float h0 = sigf(o0) * tanhf((c0 - mean2) * inv2);
    float h1 = sigf(o1) * tanhf((c1 - mean2) * inv2);

    out_c[cb + t] = c0;
    out_c[cb + t + 512] = c1;
    out_h[cb + t] = h0;
    out_h[cb + t + 512] = h1;
}

// ---------------------------------------------------------------------------
// launch — fork/join two streams so the hyper chain overlaps the big GEMMs
// ---------------------------------------------------------------------------
static cudaStream_t make_stream() {
    cudaStream_t s;
    cudaStreamCreateWithFlags(&s, cudaStreamNonBlocking);
    return s;
}
static cudaEvent_t make_event() {
    cudaEvent_t e;
    cudaEventCreateWithFlags(&e, cudaEventDisableTiming);
    return e;
}

extern "C" void kernel_launch(void* const* d_in, const int* in_sizes, int n_in,
                              void* d_out, int out_size)
{
    const float* inputs       = (const float*)d_in[0];
    const float* main_h       = (const float*)d_in[1];
    const float* main_c       = (const float*)d_in[2];
    const float* hyper_h      = (const float*)d_in[3];
    const float* hyper_c      = (const float*)d_in[4];
    const float* kernel_w     = (const float*)d_in[5];
    const float* rec_w        = (const float*)d_in[6];
    const float* bias         = (const float*)d_in[7];
    const float* hyper_kernel = (const float*)d_in[8];
    const float* hyper_rec    = (const float*)d_in[9];
    const float* hyper_bias   = (const float*)d_in[10];
    const float* dx_w         = (const float*)d_in[11];
    const float* dx_b         = (const float*)d_in[12];
    const float* dh_w         = (const float*)d_in[13];
    const float* dh_b         = (const float*)d_in[14];
    const float* db_w         = (const float*)d_in[15];
    const float* db_b         = (const float*)d_in[16];

    float* out = (float*)d_out;
    float* out_h  = out;
    float* out_c  = out + (size_t)BB * UU;
    float* out_ho = out + (size_t)2 * BB * UU;
    float* out_hc = out_ho + (size_t)BB * HHU;

    float *z, *s, *px, *phv;
    cudaGetSymbolAddress((void**)&z,   g_z);
    cudaGetSymbolAddress((void**)&s,   g_s);
    cudaGetSymbolAddress((void**)&px,  g_px);
    cudaGetSymbolAddress((void**)&phv, g_ph);

    __half *ahyp, *aho, *wthyp, *wtall, *wtk, *wtr;
    cudaGetSymbolAddress((void**)&ahyp,  g_ahyp);
    cudaGetSymbolAddress((void**)&aho,   g_aho);
    cudaGetSymbolAddress((void**)&wthyp, g_wthyp);
    cudaGetSymbolAddress((void**)&wtall, g_wtall);
    cudaGetSymbolAddress((void**)&wtk,   g_wtk);
    cudaGetSymbolAddress((void**)&wtr,   g_wtr);

    constexpr int SSZ_H = (128 + 128) * SROW;   // WN=2
    constexpr int SSZ_4 = (128 + 256) * SROW;   // WN=4
    cudaFuncSetAttribute(gemm_k<2>,  cudaFuncAttributeMaxDynamicSharedMemorySize, 2 * SSZ_H);
    cudaFuncSetAttribute(gemm_pxph, cudaFuncAttributeMaxDynamicSharedMemorySize, 2 * SSZ_4);
    cudaFuncSetAttribute(gemm_s,    cudaFuncAttributeMaxDynamicSharedMemorySize, S_SMEM);

    // One-time resources (created on first, non-capture call; reused after).
    static cudaStream_t sB = make_stream();
    static cudaEvent_t evRoot = make_event();
    static cudaEvent_t evConcat = make_event();
    static cudaEvent_t evHyper = make_event();

    dim3 tb(32, 8);

    // ---- fork side stream at graph root ----
    cudaEventRecord(evRoot, 0);
    cudaStreamWaitEvent(sB, evRoot, 0);

    // main stream: concat (needed by both branches), then big-GEMM prep + pxph
    concat_fp16<<<(BB * KHYP / 4 + 255) / 256, 256>>>(inputs, main_h, hyper_h, ahyp);
    cudaEventRecord(evConcat, 0);

    trans_kr<<<dim3(FOURU/32, UU/64, 2), tb>>>(kernel_w, rec_w, wtk, wtr);
    gemm_pxph<<<dim3(FOURU/256, BB/128, 2), 256, 2*SSZ_4>>>(
        ahyp, wtk, bias, px, ahyp + DD, wtr, phv, KHYP);

    // side stream: hyper weight prep + hyper GEMM + pointwise
    trans_hyp<<<dim3(FOURHU/32, (DD+UU)/64, 2), tb, 0, sB>>>(hyper_kernel, hyper_rec, wthyp);
    trans_d3 <<<dim3(FOURU/32, HHU/64, 3), tb, 0, sB>>>(dx_w, dh_w, db_w, wtall);
    cudaStreamWaitEvent(sB, evConcat, 0);
    gemm_k<2><<<dim3(FOURHU/128, BB/128), 128, 2*SSZ_H, sB>>>(
        ahyp, KHYP, wthyp, KHYP, hyper_bias, z, FOURHU, KHYP);
    hyper_pointwise<<<(BB * HHU + 255) / 256, 256, 0, sB>>>(z, hyper_c, out_ho, out_hc, aho);
    cudaEventRecord(evHyper, sB);

    // join: gemm_s needs px/ph (main) + aho (side)
    cudaStreamWaitEvent(0, evHyper, 0);
    gemm_s<<<dim3(FOURU/128, BB/128), 256, S_SMEM>>>(
        aho, wtall, dx_b, dh_b, db_b, px, phv, s);

    main_epilogue<<<BB, 512>>>(s, main_c, out_h, out_c);
}